// round 6
// baseline (speedup 1.0000x reference)
#include <cuda_runtime.h>
#include <math.h>

// ---------------------------------------------------------------------------
// Problem constants
// ---------------------------------------------------------------------------
#define BATCH   64
#define B2      32
#define NTOK    257
#define C       768
#define HID     3072
#define NH      12
#define HD      64
#define T       (BATCH * NTOK)      // 16448 tokens total
#define TH      (B2 * NTOK)         // 8224 tokens per half

// ---------------------------------------------------------------------------
// Scratch (static device allocations; no cudaMalloc allowed)
// ---------------------------------------------------------------------------
__device__ float g_normed[T * C];          // LN output (reused for LN2)
__device__ float g_qkv[T * 3 * C];         // QKV for all tokens
__device__ float g_attn[T * C];            // attention output pre-proj (b,n,c)
__device__ float g_x1[T * C];              // post-attention residual
__device__ float g_weff[C * C];            // effective small-branch proj weight
__device__ float g_beff[C];                // effective small-branch proj bias
__device__ float g_hL[TH * HID];           // large-branch MLP hidden (post-gelu)
__device__ float g_pre[3 * TH * HID];      // small-branch pre-acts / hiddens

// ---------------------------------------------------------------------------
// LayerNorm: one block per row (768 elems), picks large/small params by row
// ---------------------------------------------------------------------------
__global__ __launch_bounds__(256) void ln_kernel(
    const float* __restrict__ x,
    const float* __restrict__ gl, const float* __restrict__ bl,
    const float* __restrict__ gs, const float* __restrict__ bs,
    float* __restrict__ out)
{
    int row = blockIdx.x;
    const float* xr = x + (size_t)row * C;
    int t = threadIdx.x;
    float v0 = xr[t], v1 = xr[t + 256], v2 = xr[t + 512];
    float s = v0 + v1 + v2;
    float ss = v0 * v0 + v1 * v1 + v2 * v2;
    #pragma unroll
    for (int o = 16; o; o >>= 1) {
        s  += __shfl_xor_sync(0xffffffffu, s, o);
        ss += __shfl_xor_sync(0xffffffffu, ss, o);
    }
    __shared__ float sm[2][8];
    int warp = t >> 5, lane = t & 31;
    if (!lane) { sm[0][warp] = s; sm[1][warp] = ss; }
    __syncthreads();
    if (t < 32) {
        float a = (lane < 8) ? sm[0][lane] : 0.f;
        float b = (lane < 8) ? sm[1][lane] : 0.f;
        #pragma unroll
        for (int o = 4; o; o >>= 1) {
            a += __shfl_xor_sync(0xffffffffu, a, o);
            b += __shfl_xor_sync(0xffffffffu, b, o);
        }
        if (!lane) { sm[0][0] = a; sm[1][0] = b; }
    }
    __syncthreads();
    float mean = sm[0][0] * (1.0f / C);
    float var  = sm[1][0] * (1.0f / C) - mean * mean;
    float rstd = rsqrtf(var + 1e-5f);
    const float* g  = (row < TH) ? gl : gs;
    const float* bb = (row < TH) ? bl : bs;
    float* orow = out + (size_t)row * C;
    orow[t]       = (v0 - mean) * rstd * g[t]       + bb[t];
    orow[t + 256] = (v1 - mean) * rstd * g[t + 256] + bb[t + 256];
    orow[t + 512] = (v2 - mean) * rstd * g[t + 512] + bb[t + 512];
}

// ---------------------------------------------------------------------------
// Effective small-branch projection weight/bias:
//   weff[r,c] = w[r,c]*(g0 + g1*[r<384][c<384] + g2*[r<256][c<256])
// ---------------------------------------------------------------------------
__global__ void weff_kernel(const float* __restrict__ w, const float* __restrict__ b,
                            const float* __restrict__ g,
                            float* __restrict__ weff, float* __restrict__ beff)
{
    int i = blockIdx.x * blockDim.x + threadIdx.x;
    if (i < C * C) {
        int r = i / C, c = i % C;
        float m = g[0];
        if (r < 384 && c < 384) m += g[1];
        if (r < 256 && c < 256) m += g[2];
        weff[i] = w[i] * m;
    }
    if (i < C) {
        float m = g[0];
        if (i < 384) m += g[1];
        if (i < 256) m += g[2];
        beff[i] = b[i] * m;
    }
}

// ---------------------------------------------------------------------------
// Classic 128x128x8 register-blocked SGEMM, fused epilogue:
//   C[r,c] = alpha*(A@B + bias[c]) + Cin[r,c] + resid[r,c]; optional exact GELU.
// N and K must be multiples of 128 / 8 (true for every call site);
// M is guarded.  alpha read from device pointer (gumbel weight) if non-null.
// ---------------------------------------------------------------------------
__global__ __launch_bounds__(256) void sgemm_k(
    const float* __restrict__ A, int lda,
    const float* __restrict__ B, int ldb,
    float* __restrict__ Cc, int ldc,
    const float* __restrict__ Cin, int ldcin,
    const float* __restrict__ bias,
    const float* __restrict__ resid, int ldr,
    int M, int K,
    const float* __restrict__ alpha_ptr, int aidx,
    int do_gelu)
{
    __shared__ float As[8][128];
    __shared__ float Bs[8][128];
    int tid = threadIdx.x;
    int bn = blockIdx.x, bm = blockIdx.y;

    int rowA = tid >> 1;
    int colA = (tid & 1) << 2;
    int rowB = tid >> 5;
    int colB = (tid & 31) << 2;

    const float* Aptr = A + (size_t)(bm * 128 + rowA) * lda + colA;
    const float* Bptr = B + (size_t)rowB * ldb + bn * 128 + colB;
    bool aValid = (bm * 128 + rowA) < M;

    int tr = (tid >> 4) << 3;   // thread row base within tile
    int tc = (tid & 15) << 3;   // thread col base within tile

    float acc[8][8];
    #pragma unroll
    for (int i = 0; i < 8; i++)
        #pragma unroll
        for (int j = 0; j < 8; j++) acc[i][j] = 0.f;

    for (int k0 = 0; k0 < K; k0 += 8) {
        float4 av = aValid ? *(const float4*)Aptr : make_float4(0.f, 0.f, 0.f, 0.f);
        float4 bv = *(const float4*)Bptr;
        __syncthreads();
        As[colA + 0][rowA] = av.x;
        As[colA + 1][rowA] = av.y;
        As[colA + 2][rowA] = av.z;
        As[colA + 3][rowA] = av.w;
        *(float4*)&Bs[rowB][colB] = bv;
        __syncthreads();
        #pragma unroll
        for (int k = 0; k < 8; k++) {
            float ar[8], br[8];
            #pragma unroll
            for (int i = 0; i < 8; i++) ar[i] = As[k][tr + i];
            #pragma unroll
            for (int j = 0; j < 8; j++) br[j] = Bs[k][tc + j];
            #pragma unroll
            for (int i = 0; i < 8; i++)
                #pragma unroll
                for (int j = 0; j < 8; j++) acc[i][j] += ar[i] * br[j];
        }
        Aptr += 8;
        Bptr += (size_t)8 * ldb;
    }

    float alpha = alpha_ptr ? alpha_ptr[aidx] : 1.0f;
    #pragma unroll
    for (int i = 0; i < 8; i++) {
        int r = bm * 128 + tr + i;
        if (r >= M) continue;
        #pragma unroll
        for (int j = 0; j < 8; j++) {
            int c = bn * 128 + tc + j;
            float v = acc[i][j];
            if (bias)  v += bias[c];
            v *= alpha;
            if (Cin)   v += Cin[(size_t)r * ldcin + c];
            if (resid) v += resid[(size_t)r * ldr + c];
            if (do_gelu) v = 0.5f * v * (1.0f + erff(v * 0.70710678118654752f));
            Cc[(size_t)r * ldc + c] = v;
        }
    }
}

// ---------------------------------------------------------------------------
// Attention: one block per (b, h).  K,V resident in smem (padded rows),
// 8 warps each own queries n = warp, warp+8, ...
// ---------------------------------------------------------------------------
#define KPITCH 65
#define PSTRIDE 264

__global__ __launch_bounds__(256) void attn_kernel(
    const float* __restrict__ qkv, float* __restrict__ out)
{
    int bh = blockIdx.x;
    int b = bh / NH, h = bh % NH;
    extern __shared__ float smem[];
    float* Ksh = smem;                          // 257*65
    float* Vsh = Ksh + NTOK * KPITCH;           // 257*65
    float* Psh = Vsh + NTOK * KPITCH;           // 8*264
    float* Qsh = Psh + 8 * PSTRIDE;             // 8*64

    int tid = threadIdx.x, warp = tid >> 5, lane = tid & 31;
    const float* base = qkv + (size_t)b * NTOK * (3 * C);

    for (int idx = tid; idx < NTOK * HD; idx += 256) {
        int m = idx / HD, d = idx % HD;
        const float* row = base + (size_t)m * (3 * C) + h * HD + d;
        Ksh[m * KPITCH + d] = row[C];
        Vsh[m * KPITCH + d] = row[2 * C];
    }
    __syncthreads();

    float* myP = Psh + warp * PSTRIDE;
    float* myQ = Qsh + warp * HD;

    for (int n = warp; n < NTOK; n += 8) {
        const float* qrow = base + (size_t)n * (3 * C) + h * HD;
        myQ[lane]      = qrow[lane];
        myQ[lane + 32] = qrow[lane + 32];
        __syncwarp();

        float lmax = -1e30f;
        for (int m = lane; m < NTOK; m += 32) {
            const float* kr = &Ksh[m * KPITCH];
            float s0 = 0.f, s1 = 0.f, s2 = 0.f, s3 = 0.f;
            #pragma unroll
            for (int d = 0; d < HD; d += 4) {
                s0 += myQ[d]     * kr[d];
                s1 += myQ[d + 1] * kr[d + 1];
                s2 += myQ[d + 2] * kr[d + 2];
                s3 += myQ[d + 3] * kr[d + 3];
            }
            float s = ((s0 + s1) + (s2 + s3)) * 0.125f;
            myP[m] = s;
            lmax = fmaxf(lmax, s);
        }
        #pragma unroll
        for (int o = 16; o; o >>= 1)
            lmax = fmaxf(lmax, __shfl_xor_sync(0xffffffffu, lmax, o));

        float lsum = 0.f;
        for (int m = lane; m < NTOK; m += 32) {
            float p = expf(myP[m] - lmax);
            myP[m] = p;
            lsum += p;
        }
        #pragma unroll
        for (int o = 16; o; o >>= 1)
            lsum += __shfl_xor_sync(0xffffffffu, lsum, o);
        __syncwarp();

        float a0[4] = {0.f, 0.f, 0.f, 0.f};
        float a1[4] = {0.f, 0.f, 0.f, 0.f};
        int m = 0;
        for (; m + 4 <= NTOK; m += 4) {
            #pragma unroll
            for (int u = 0; u < 4; u++) {
                float p = myP[m + u];
                a0[u] += p * Vsh[(m + u) * KPITCH + lane];
                a1[u] += p * Vsh[(m + u) * KPITCH + 32 + lane];
            }
        }
        for (; m < NTOK; m++) {
            float p = myP[m];
            a0[0] += p * Vsh[m * KPITCH + lane];
            a1[0] += p * Vsh[m * KPITCH + 32 + lane];
        }
        float inv = 1.0f / lsum;
        float o0 = (a0[0] + a0[1] + a0[2] + a0[3]) * inv;
        float o1 = (a1[0] + a1[1] + a1[2] + a1[3]) * inv;

        float* orow = out + ((size_t)b * NTOK + n) * C + h * HD;
        orow[lane]      = o0;
        orow[lane + 32] = o1;
        __syncwarp();
    }
}

// ---------------------------------------------------------------------------
// Exact GELU elementwise (vectorized) for small-branch pre-activations
// ---------------------------------------------------------------------------
__device__ __forceinline__ float gelu_exact(float v) {
    return 0.5f * v * (1.0f + erff(v * 0.70710678118654752f));
}

__global__ void gelu4_kernel(float4* __restrict__ p, int n4)
{
    int i = blockIdx.x * blockDim.x + threadIdx.x;
    if (i < n4) {
        float4 v = p[i];
        v.x = gelu_exact(v.x); v.y = gelu_exact(v.y);
        v.z = gelu_exact(v.z); v.w = gelu_exact(v.w);
        p[i] = v;
    }
}

// ---------------------------------------------------------------------------
// Launch
// ---------------------------------------------------------------------------
static inline float* sym(const void* symbol) {
    void* p = nullptr;
    cudaGetSymbolAddress(&p, symbol);
    return (float*)p;
}

extern "C" void kernel_launch(void* const* d_in, const int* in_sizes, int n_in,
                              void* d_out, int out_size)
{
    const float* x      = (const float*)d_in[0];
    const float* gw     = (const float*)d_in[1];
    const float* n1l_g  = (const float*)d_in[2];
    const float* n1l_b  = (const float*)d_in[3];
    const float* n1s_g  = (const float*)d_in[4];
    const float* n1s_b  = (const float*)d_in[5];
    const float* w_qkv  = (const float*)d_in[6];
    const float* w_proj = (const float*)d_in[7];
    const float* b_proj = (const float*)d_in[8];
    const float* n2l_g  = (const float*)d_in[9];
    const float* n2l_b  = (const float*)d_in[10];
    const float* n2s_g  = (const float*)d_in[11];
    const float* n2s_b  = (const float*)d_in[12];
    const float* w_fc1  = (const float*)d_in[13];
    const float* b_fc1  = (const float*)d_in[14];
    const float* w_fc2  = (const float*)d_in[15];
    const float* b_fc2  = (const float*)d_in[16];
    float* out = (float*)d_out;

    float* normed = sym(g_normed);
    float* qkv    = sym(g_qkv);
    float* attn   = sym(g_attn);
    float* x1     = sym(g_x1);
    float* weff   = sym(g_weff);
    float* beff   = sym(g_beff);
    float* hL     = sym(g_hL);
    float* pre    = sym(g_pre);
    float* pre1 = pre;                       // full-K pre-act  (alpha=1 branch)
    float* pre2 = pre + (size_t)TH * HID;    // K<=384          (alpha=2 branch)
    float* pre3 = pre + (size_t)2 * TH * HID;// K<=256          (alpha=3 branch)

    const int attn_smem = (2 * NTOK * KPITCH + 8 * PSTRIDE + 8 * HD) * sizeof(float);
    cudaFuncSetAttribute(attn_kernel, cudaFuncAttributeMaxDynamicSharedMemorySize,
                         attn_smem);

    // 1. LN1 over all tokens
    ln_kernel<<<T, 256>>>(x, n1l_g, n1l_b, n1s_g, n1s_b, normed);

    // 2. Effective small-branch projection weights
    weff_kernel<<<(C * C + 255) / 256, 256>>>(w_proj, b_proj, gw, weff, beff);

    // 3. QKV: (T x 768) @ (768 x 2304)
    sgemm_k<<<dim3(2304 / 128, (T + 127) / 128), 256>>>(
        normed, C, w_qkv, 3 * C, qkv, 3 * C,
        nullptr, 0, nullptr, nullptr, 0, T, C, nullptr, 0, 0);

    // 4. Attention per (b,h)
    attn_kernel<<<BATCH * NH, 256, attn_smem>>>(qkv, attn);

    // 5. Projection + residual
    //    large half: w_proj/b_proj;  small half: W_eff/b_eff (masks+gumbel folded in)
    sgemm_k<<<dim3(C / 128, (TH + 127) / 128), 256>>>(
        attn, C, w_proj, C, x1, C,
        nullptr, 0, b_proj, x, C, TH, C, nullptr, 0, 0);
    sgemm_k<<<dim3(C / 128, (TH + 127) / 128), 256>>>(
        attn + (size_t)TH * C, C, weff, C, x1 + (size_t)TH * C, C,
        nullptr, 0, beff, x + (size_t)TH * C, C, TH, C, nullptr, 0, 0);

    // 6. LN2
    ln_kernel<<<T, 256>>>(x1, n2l_g, n2l_b, n2s_g, n2s_b, normed);

    // 7. FC1
    // large: fused gelu
    sgemm_k<<<dim3(HID / 128, (TH + 127) / 128), 256>>>(
        normed, C, w_fc1, HID, hL, HID,
        nullptr, 0, b_fc1, nullptr, 0, TH, C, nullptr, 0, 1);
    // small partial-K accumulation: pre3 (K=256) -> pre2 (+K 256:384) -> pre1 (+K 384:768)
    const float* ns2 = normed + (size_t)TH * C;
    sgemm_k<<<dim3(HID / 128, (TH + 127) / 128), 256>>>(
        ns2, C, w_fc1, HID, pre3, HID,
        nullptr, 0, b_fc1, nullptr, 0, TH, 256, nullptr, 0, 0);
    sgemm_k<<<dim3(HID / 128, (TH + 127) / 128), 256>>>(
        ns2 + 256, C, w_fc1 + (size_t)256 * HID, HID, pre2, HID,
        pre3, HID, nullptr, nullptr, 0, TH, 128, nullptr, 0, 0);
    sgemm_k<<<dim3(HID / 128, (TH + 127) / 128), 256>>>(
        ns2 + 384, C, w_fc1 + (size_t)384 * HID, HID, pre1, HID,
        pre2, HID, nullptr, nullptr, 0, TH, 384, nullptr, 0, 0);
    // gelu all three small hiddens in one pass
    {
        int n4 = (3 * TH * HID) / 4;
        gelu4_kernel<<<(n4 + 255) / 256, 256>>>((float4*)pre, n4);
    }

    // 8. FC2
    // large half: + bias + residual -> out
    sgemm_k<<<dim3(C / 128, (TH + 127) / 128), 256>>>(
        hL, HID, w_fc2, C, out, C,
        nullptr, 0, b_fc2, x1, C, TH, HID, nullptr, 0, 0);
    // small half: out = x1 + g0*(h1@W2+b2) then += g1*(h2@W2[:, :384]+b2)
    //                                      then += g2*(h3@W2[:, :256]+b2)
    float* outS = out + (size_t)TH * C;
    const float* x1S = x1 + (size_t)TH * C;
    sgemm_k<<<dim3(C / 128, (TH + 127) / 128), 256>>>(
        pre1, HID, w_fc2, C, outS, C,
        nullptr, 0, b_fc2, x1S, C, TH, HID, gw, 0, 0);
    sgemm_k<<<dim3(384 / 128, (TH + 127) / 128), 256>>>(
        pre2, HID, w_fc2, C, outS, C,
        outS, C, b_fc2, nullptr, 0, TH, HID, gw, 1, 0);
    sgemm_k<<<dim3(256 / 128, (TH + 127) / 128), 256>>>(
        pre3, HID, w_fc2, C, outS, C,
        outS, C, b_fc2, nullptr, 0, TH, HID, gw, 2, 0);
}

// round 10
// speedup vs baseline: 2.4190x; 2.4190x over previous
#include <cuda_runtime.h>
#include <math.h>
#include <stdint.h>

// ---------------------------------------------------------------------------
// Problem constants
// ---------------------------------------------------------------------------
#define BATCH   64
#define B2      32
#define NTOK    257
#define C       768
#define HID     3072
#define NH      12
#define HD      64
#define T       (BATCH * NTOK)      // 16448 tokens total
#define TH      (B2 * NTOK)         // 8224 tokens per half

// ---------------------------------------------------------------------------
// Scratch (static device allocations; no cudaMalloc allowed)
// ---------------------------------------------------------------------------
__device__ float g_normed[T * C];
__device__ float g_qkv[T * 3 * C];
__device__ float g_attn[T * C];
__device__ float g_x1[T * C];
__device__ float g_weff[C * C];
__device__ float g_beff[C];
__device__ float g_hL[TH * HID];
__device__ float g_pre[3 * TH * HID];

// ---------------------------------------------------------------------------
// Helpers
// ---------------------------------------------------------------------------
__device__ __forceinline__ float to_tf32(float x) {
    float r;
    asm("cvt.rna.tf32.f32 %0, %1;" : "=f"(r) : "f"(x));
    return r;
}
__device__ __forceinline__ float gelu_exact(float v) {
    return 0.5f * v * (1.0f + erff(v * 0.70710678118654752f));
}

// mma.sync m16n8k8 tf32: D(4f) = A(4r) * B(2r) + D
__device__ __forceinline__ void mma_tf32(float* c, const uint32_t* a, const uint32_t* b) {
    asm volatile(
        "mma.sync.aligned.m16n8k8.row.col.f32.tf32.tf32.f32 "
        "{%0,%1,%2,%3}, {%4,%5,%6,%7}, {%8,%9}, {%0,%1,%2,%3};"
        : "+f"(c[0]), "+f"(c[1]), "+f"(c[2]), "+f"(c[3])
        : "r"(a[0]), "r"(a[1]), "r"(a[2]), "r"(a[3]), "r"(b[0]), "r"(b[1]));
}

// single extern shared symbol shared by all kernels
extern __shared__ char dsmem[];

// smem GEMM layout (floats)
#define APITCH 36
#define BPITCH 136
#define ASZ (128 * APITCH)          // 4608 floats
#define BSZ (32 * BPITCH)           // 4352 floats
#define GEMM_SMEM ((2 * (ASZ + BSZ)) * 4)   // 71680 bytes

// ---------------------------------------------------------------------------
// tf32 tensor-core GEMM: C[128m x 128n] tile per CTA, BK=32 double-buffered.
// Epilogue: v = alpha*(acc + bias[c]); v += Cin; v += resid; optional GELU.
// N, K multiples of 128 / 32 at every call site; M guarded.
// ---------------------------------------------------------------------------
__global__ void __launch_bounds__(256, 1) tgemm_k(
    const float* __restrict__ A, int lda,
    const float* __restrict__ B, int ldb,
    float* __restrict__ Cc, int ldc,
    const float* __restrict__ Cin, int ldcin,
    const float* __restrict__ bias,
    const float* __restrict__ resid, int ldr,
    int M, int K,
    const float* __restrict__ alpha_ptr, int aidx,
    int do_gelu)
{
    float* smf = (float*)dsmem;
    float* As[2] = { smf, smf + ASZ };
    float* Bs[2] = { smf + 2 * ASZ, smf + 2 * ASZ + BSZ };

    const int tid = threadIdx.x;
    const int wid = tid >> 5, lid = tid & 31;
    const int warpM = wid >> 2;          // 0..1  (64 rows each)
    const int warpN = wid & 3;           // 0..3  (32 cols each)
    const int lq = lid >> 2;             // 0..7
    const int lr = lid & 3;              // 0..3
    const int bn = blockIdx.x, bm = blockIdx.y;

    // gmem load coords (per thread, 4 float4 each for A and B per chunk)
    const int arow = tid >> 3;           // wrong granularity fixed in loop (f-based)
    (void)arow;

    float4 aR[4], bR[4];
    float acc[4][4][4];
    #pragma unroll
    for (int mi = 0; mi < 4; mi++)
        #pragma unroll
        for (int ni = 0; ni < 4; ni++)
            #pragma unroll
            for (int j = 0; j < 4; j++) acc[mi][ni][j] = 0.f;

    const int nch = K >> 5;

    // ---- chunk loaders ----
    auto loadA = [&](int ci) {
        int k0 = ci << 5;
        #pragma unroll
        for (int u = 0; u < 4; u++) {
            int f = tid + u * 256;               // 1024 float4
            int row = f >> 3, c4 = f & 7;
            int r = bm * 128 + row;
            float4 v = make_float4(0.f, 0.f, 0.f, 0.f);
            if (r < M) v = *(const float4*)(A + (size_t)r * lda + k0 + c4 * 4);
            v.x = to_tf32(v.x); v.y = to_tf32(v.y);
            v.z = to_tf32(v.z); v.w = to_tf32(v.w);
            aR[u] = v;
        }
    };
    auto loadB = [&](int ci) {
        int k0 = ci << 5;
        #pragma unroll
        for (int u = 0; u < 4; u++) {
            int f = tid + u * 256;               // 1024 float4
            int kk = f >> 5, n4 = f & 31;
            float4 v = *(const float4*)(B + (size_t)(k0 + kk) * ldb + bn * 128 + n4 * 4);
            v.x = to_tf32(v.x); v.y = to_tf32(v.y);
            v.z = to_tf32(v.z); v.w = to_tf32(v.w);
            bR[u] = v;
        }
    };
    auto storeAB = [&](int buf) {
        #pragma unroll
        for (int u = 0; u < 4; u++) {
            int f = tid + u * 256;
            int row = f >> 3, c4 = f & 7;
            float* d = As[buf] + row * APITCH + c4 * 4;
            d[0] = aR[u].x; d[1] = aR[u].y; d[2] = aR[u].z; d[3] = aR[u].w;
        }
        #pragma unroll
        for (int u = 0; u < 4; u++) {
            int f = tid + u * 256;
            int kk = f >> 5, n4 = f & 31;
            float* d = Bs[buf] + kk * BPITCH + n4 * 4;
            d[0] = bR[u].x; d[1] = bR[u].y; d[2] = bR[u].z; d[3] = bR[u].w;
        }
    };

    // preload chunk 0
    loadA(0); loadB(0);
    storeAB(0);
    __syncthreads();

    for (int i = 0; i < nch; i++) {
        int buf = i & 1;
        if (i + 1 < nch) { loadA(i + 1); loadB(i + 1); }

        // compute on buf
        const uint32_t* ap = (const uint32_t*)As[buf];
        const uint32_t* bp = (const uint32_t*)Bs[buf];
        #pragma unroll
        for (int ks = 0; ks < 4; ks++) {
            int k0 = ks << 3;
            uint32_t afr[4][4], bfr[4][2];
            #pragma unroll
            for (int mi = 0; mi < 4; mi++) {
                int m0 = warpM * 64 + mi * 16 + lq;
                afr[mi][0] = ap[m0 * APITCH + k0 + lr];
                afr[mi][1] = ap[(m0 + 8) * APITCH + k0 + lr];
                afr[mi][2] = ap[m0 * APITCH + k0 + lr + 4];
                afr[mi][3] = ap[(m0 + 8) * APITCH + k0 + lr + 4];
            }
            #pragma unroll
            for (int ni = 0; ni < 4; ni++) {
                int n0 = warpN * 32 + ni * 8 + lq;
                bfr[ni][0] = bp[(k0 + lr) * BPITCH + n0];
                bfr[ni][1] = bp[(k0 + lr + 4) * BPITCH + n0];
            }
            #pragma unroll
            for (int mi = 0; mi < 4; mi++)
                #pragma unroll
                for (int ni = 0; ni < 4; ni++)
                    mma_tf32(acc[mi][ni], afr[mi], bfr[ni]);
        }

        if (i + 1 < nch) storeAB((i + 1) & 1);
        __syncthreads();
    }

    // ---- epilogue: registers -> gmem with fused ops ----
    float alpha = alpha_ptr ? alpha_ptr[aidx] : 1.0f;
    #pragma unroll
    for (int mi = 0; mi < 4; mi++) {
        #pragma unroll
        for (int h = 0; h < 2; h++) {
            int r = bm * 128 + warpM * 64 + mi * 16 + lq + h * 8;
            if (r >= M) continue;
            #pragma unroll
            for (int ni = 0; ni < 4; ni++) {
                int cc = bn * 128 + warpN * 32 + ni * 8 + lr * 2;
                float v0 = acc[mi][ni][h * 2 + 0];
                float v1 = acc[mi][ni][h * 2 + 1];
                if (bias) { v0 += bias[cc]; v1 += bias[cc + 1]; }
                v0 *= alpha; v1 *= alpha;
                if (Cin) {
                    const float* cp = Cin + (size_t)r * ldcin + cc;
                    v0 += cp[0]; v1 += cp[1];
                }
                if (resid) {
                    const float* rp = resid + (size_t)r * ldr + cc;
                    v0 += rp[0]; v1 += rp[1];
                }
                if (do_gelu) { v0 = gelu_exact(v0); v1 = gelu_exact(v1); }
                float2* op = (float2*)(Cc + (size_t)r * ldc + cc);
                *op = make_float2(v0, v1);
            }
        }
    }
}

// ---------------------------------------------------------------------------
// LayerNorm: one block per row (768 elems), picks large/small params by row
// ---------------------------------------------------------------------------
__global__ __launch_bounds__(256) void ln_kernel(
    const float* __restrict__ x,
    const float* __restrict__ gl, const float* __restrict__ bl,
    const float* __restrict__ gs, const float* __restrict__ bs,
    float* __restrict__ out)
{
    int row = blockIdx.x;
    const float* xr = x + (size_t)row * C;
    int t = threadIdx.x;
    float v0 = xr[t], v1 = xr[t + 256], v2 = xr[t + 512];
    float s = v0 + v1 + v2;
    float ss = v0 * v0 + v1 * v1 + v2 * v2;
    #pragma unroll
    for (int o = 16; o; o >>= 1) {
        s  += __shfl_xor_sync(0xffffffffu, s, o);
        ss += __shfl_xor_sync(0xffffffffu, ss, o);
    }
    __shared__ float sm[2][8];
    int warp = t >> 5, lane = t & 31;
    if (!lane) { sm[0][warp] = s; sm[1][warp] = ss; }
    __syncthreads();
    if (t < 32) {
        float a = (lane < 8) ? sm[0][lane] : 0.f;
        float b = (lane < 8) ? sm[1][lane] : 0.f;
        #pragma unroll
        for (int o = 4; o; o >>= 1) {
            a += __shfl_xor_sync(0xffffffffu, a, o);
            b += __shfl_xor_sync(0xffffffffu, b, o);
        }
        if (!lane) { sm[0][0] = a; sm[1][0] = b; }
    }
    __syncthreads();
    float mean = sm[0][0] * (1.0f / C);
    float var  = sm[1][0] * (1.0f / C) - mean * mean;
    float rstd = rsqrtf(var + 1e-5f);
    const float* g  = (row < TH) ? gl : gs;
    const float* bb = (row < TH) ? bl : bs;
    float* orow = out + (size_t)row * C;
    orow[t]       = (v0 - mean) * rstd * g[t]       + bb[t];
    orow[t + 256] = (v1 - mean) * rstd * g[t + 256] + bb[t + 256];
    orow[t + 512] = (v2 - mean) * rstd * g[t + 512] + bb[t + 512];
}

// ---------------------------------------------------------------------------
// Effective small-branch projection weight/bias
// ---------------------------------------------------------------------------
__global__ void weff_kernel(const float* __restrict__ w, const float* __restrict__ b,
                            const float* __restrict__ g,
                            float* __restrict__ weff, float* __restrict__ beff)
{
    int i = blockIdx.x * blockDim.x + threadIdx.x;
    if (i < C * C) {
        int r = i / C, c = i % C;
        float m = g[0];
        if (r < 384 && c < 384) m += g[1];
        if (r < 256 && c < 256) m += g[2];
        weff[i] = w[i] * m;
    }
    if (i < C) {
        float m = g[0];
        if (i < 384) m += g[1];
        if (i < 256) m += g[2];
        beff[i] = b[i] * m;
    }
}

// ---------------------------------------------------------------------------
// Attention: one block per (b, h)
// ---------------------------------------------------------------------------
#define KPITCH 65
#define PSTRIDE 264

__global__ __launch_bounds__(256) void attn_kernel(
    const float* __restrict__ qkv, float* __restrict__ out)
{
    int bh = blockIdx.x;
    int b = bh / NH, h = bh % NH;
    float* smemf = (float*)dsmem;
    float* Ksh = smemf;
    float* Vsh = Ksh + NTOK * KPITCH;
    float* Psh = Vsh + NTOK * KPITCH;
    float* Qsh = Psh + 8 * PSTRIDE;

    int tid = threadIdx.x, warp = tid >> 5, lane = tid & 31;
    const float* base = qkv + (size_t)b * NTOK * (3 * C);

    for (int idx = tid; idx < NTOK * HD; idx += 256) {
        int m = idx / HD, d = idx % HD;
        const float* row = base + (size_t)m * (3 * C) + h * HD + d;
        Ksh[m * KPITCH + d] = row[C];
        Vsh[m * KPITCH + d] = row[2 * C];
    }
    __syncthreads();

    float* myP = Psh + warp * PSTRIDE;
    float* myQ = Qsh + warp * HD;

    for (int n = warp; n < NTOK; n += 8) {
        const float* qrow = base + (size_t)n * (3 * C) + h * HD;
        myQ[lane]      = qrow[lane];
        myQ[lane + 32] = qrow[lane + 32];
        __syncwarp();

        float lmax = -1e30f;
        for (int m = lane; m < NTOK; m += 32) {
            const float* kr = &Ksh[m * KPITCH];
            float s0 = 0.f, s1 = 0.f, s2 = 0.f, s3 = 0.f;
            #pragma unroll
            for (int d = 0; d < HD; d += 4) {
                s0 += myQ[d]     * kr[d];
                s1 += myQ[d + 1] * kr[d + 1];
                s2 += myQ[d + 2] * kr[d + 2];
                s3 += myQ[d + 3] * kr[d + 3];
            }
            float s = ((s0 + s1) + (s2 + s3)) * 0.125f;
            myP[m] = s;
            lmax = fmaxf(lmax, s);
        }
        #pragma unroll
        for (int o = 16; o; o >>= 1)
            lmax = fmaxf(lmax, __shfl_xor_sync(0xffffffffu, lmax, o));

        float lsum = 0.f;
        for (int m = lane; m < NTOK; m += 32) {
            float p = expf(myP[m] - lmax);
            myP[m] = p;
            lsum += p;
        }
        #pragma unroll
        for (int o = 16; o; o >>= 1)
            lsum += __shfl_xor_sync(0xffffffffu, lsum, o);
        __syncwarp();

        float a0[4] = {0.f, 0.f, 0.f, 0.f};
        float a1[4] = {0.f, 0.f, 0.f, 0.f};
        int m = 0;
        for (; m + 4 <= NTOK; m += 4) {
            #pragma unroll
            for (int u = 0; u < 4; u++) {
                float p = myP[m + u];
                a0[u] += p * Vsh[(m + u) * KPITCH + lane];
                a1[u] += p * Vsh[(m + u) * KPITCH + 32 + lane];
            }
        }
        for (; m < NTOK; m++) {
            float p = myP[m];
            a0[0] += p * Vsh[m * KPITCH + lane];
            a1[0] += p * Vsh[m * KPITCH + 32 + lane];
        }
        float inv = 1.0f / lsum;
        float o0 = (a0[0] + a0[1] + a0[2] + a0[3]) * inv;
        float o1 = (a1[0] + a1[1] + a1[2] + a1[3]) * inv;

        float* orow = out + ((size_t)b * NTOK + n) * C + h * HD;
        orow[lane]      = o0;
        orow[lane + 32] = o1;
        __syncwarp();
    }
}

// ---------------------------------------------------------------------------
// Exact GELU elementwise (vectorized)
// ---------------------------------------------------------------------------
__global__ void gelu4_kernel(float4* __restrict__ p, int n4)
{
    int i = blockIdx.x * blockDim.x + threadIdx.x;
    if (i < n4) {
        float4 v = p[i];
        v.x = gelu_exact(v.x); v.y = gelu_exact(v.y);
        v.z = gelu_exact(v.z); v.w = gelu_exact(v.w);
        p[i] = v;
    }
}

// ---------------------------------------------------------------------------
// Launch
// ---------------------------------------------------------------------------
static inline float* sym(const void* symbol) {
    void* p = nullptr;
    cudaGetSymbolAddress(&p, symbol);
    return (float*)p;
}

extern "C" void kernel_launch(void* const* d_in, const int* in_sizes, int n_in,
                              void* d_out, int out_size)
{
    const float* x      = (const float*)d_in[0];
    const float* gw     = (const float*)d_in[1];
    const float* n1l_g  = (const float*)d_in[2];
    const float* n1l_b  = (const float*)d_in[3];
    const float* n1s_g  = (const float*)d_in[4];
    const float* n1s_b  = (const float*)d_in[5];
    const float* w_qkv  = (const float*)d_in[6];
    const float* w_proj = (const float*)d_in[7];
    const float* b_proj = (const float*)d_in[8];
    const float* n2l_g  = (const float*)d_in[9];
    const float* n2l_b  = (const float*)d_in[10];
    const float* n2s_g  = (const float*)d_in[11];
    const float* n2s_b  = (const float*)d_in[12];
    const float* w_fc1  = (const float*)d_in[13];
    const float* b_fc1  = (const float*)d_in[14];
    const float* w_fc2  = (const float*)d_in[15];
    const float* b_fc2  = (const float*)d_in[16];
    float* out = (float*)d_out;

    float* normed = sym(g_normed);
    float* qkv    = sym(g_qkv);
    float* attn   = sym(g_attn);
    float* x1     = sym(g_x1);
    float* weff   = sym(g_weff);
    float* beff   = sym(g_beff);
    float* hL     = sym(g_hL);
    float* pre    = sym(g_pre);
    float* pre1 = pre;                        // full-K pre-act  (alpha g0)
    float* pre2 = pre + (size_t)TH * HID;     // K<=384          (alpha g1)
    float* pre3 = pre + (size_t)2 * TH * HID; // K<=256          (alpha g2)

    const int attn_smem = (2 * NTOK * KPITCH + 8 * PSTRIDE + 8 * HD) * sizeof(float);
    cudaFuncSetAttribute(attn_kernel, cudaFuncAttributeMaxDynamicSharedMemorySize,
                         attn_smem);
    cudaFuncSetAttribute(tgemm_k, cudaFuncAttributeMaxDynamicSharedMemorySize,
                         GEMM_SMEM);

    const int MB_T  = (T  + 127) / 128;   // 129
    const int MB_TH = (TH + 127) / 128;   // 65

    // 1. LN1 over all tokens
    ln_kernel<<<T, 256>>>(x, n1l_g, n1l_b, n1s_g, n1s_b, normed);

    // 2. Effective small-branch projection weights
    weff_kernel<<<(C * C + 255) / 256, 256>>>(w_proj, b_proj, gw, weff, beff);

    // 3. QKV: (T x 768) @ (768 x 2304)
    tgemm_k<<<dim3(2304 / 128, MB_T), 256, GEMM_SMEM>>>(
        normed, C, w_qkv, 3 * C, qkv, 3 * C,
        nullptr, 0, nullptr, nullptr, 0, T, C, nullptr, 0, 0);

    // 4. Attention per (b,h)
    attn_kernel<<<BATCH * NH, 256, attn_smem>>>(qkv, attn);

    // 5. Projection + residual (large: w_proj; small: folded W_eff)
    tgemm_k<<<dim3(C / 128, MB_TH), 256, GEMM_SMEM>>>(
        attn, C, w_proj, C, x1, C,
        nullptr, 0, b_proj, x, C, TH, C, nullptr, 0, 0);
    tgemm_k<<<dim3(C / 128, MB_TH), 256, GEMM_SMEM>>>(
        attn + (size_t)TH * C, C, weff, C, x1 + (size_t)TH * C, C,
        nullptr, 0, beff, x + (size_t)TH * C, C, TH, C, nullptr, 0, 0);

    // 6. LN2
    ln_kernel<<<T, 256>>>(x1, n2l_g, n2l_b, n2s_g, n2s_b, normed);

    // 7. FC1
    tgemm_k<<<dim3(HID / 128, MB_TH), 256, GEMM_SMEM>>>(
        normed, C, w_fc1, HID, hL, HID,
        nullptr, 0, b_fc1, nullptr, 0, TH, C, nullptr, 0, 1);
    const float* ns2 = normed + (size_t)TH * C;
    // small partial-K chain: pre3 (K=256) -> pre2 (+K 256:384) -> pre1 (+K 384:768, fused gelu)
    tgemm_k<<<dim3(HID / 128, MB_TH), 256, GEMM_SMEM>>>(
        ns2, C, w_fc1, HID, pre3, HID,
        nullptr, 0, b_fc1, nullptr, 0, TH, 256, nullptr, 0, 0);
    tgemm_k<<<dim3(HID / 128, MB_TH), 256, GEMM_SMEM>>>(
        ns2 + 256, C, w_fc1 + (size_t)256 * HID, HID, pre2, HID,
        pre3, HID, nullptr, nullptr, 0, TH, 128, nullptr, 0, 0);
    tgemm_k<<<dim3(HID / 128, MB_TH), 256, GEMM_SMEM>>>(
        ns2 + 384, C, w_fc1 + (size_t)384 * HID, HID, pre1, HID,
        pre2, HID, nullptr, nullptr, 0, TH, 384, nullptr, 0, 1);
    // gelu pre2 & pre3 (pre1 already gelu'd in epilogue)
    {
        int n4 = (2 * TH * HID) / 4;
        gelu4_kernel<<<(n4 + 255) / 256, 256>>>((float4*)pre2, n4);
    }

    // 8. FC2
    tgemm_k<<<dim3(C / 128, MB_TH), 256, GEMM_SMEM>>>(
        hL, HID, w_fc2, C, out, C,
        nullptr, 0, b_fc2, x1, C, TH, HID, nullptr, 0, 0);
    float* outS = out + (size_t)TH * C;
    const float* x1S = x1 + (size_t)TH * C;
    tgemm_k<<<dim3(C / 128, MB_TH), 256, GEMM_SMEM>>>(
        pre1, HID, w_fc2, C, outS, C,
        nullptr, 0, b_fc2, x1S, C, TH, HID, gw, 0, 0);
    tgemm_k<<<dim3(384 / 128, MB_TH), 256, GEMM_SMEM>>>(
        pre2, HID, w_fc2, C, outS, C,
        outS, C, b_fc2, nullptr, 0, TH, HID, gw, 1, 0);
    tgemm_k<<<dim3(256 / 128, MB_TH), 256, GEMM_SMEM>>>(
        pre3, HID, w_fc2, C, outS, C,
        outS, C, b_fc2, nullptr, 0, TH, HID, gw, 2, 0);
}

// round 11
// speedup vs baseline: 4.2719x; 1.7659x over previous
#include <cuda_runtime.h>
#include <math.h>
#include <stdint.h>

// ---------------------------------------------------------------------------
// Problem constants
// ---------------------------------------------------------------------------
#define BATCH   64
#define B2      32
#define NTOK    257
#define C       768
#define HID     3072
#define NH      12
#define HD      64
#define T       (BATCH * NTOK)      // 16448 tokens total
#define TH      (B2 * NTOK)         // 8224 tokens per half

// ---------------------------------------------------------------------------
// Scratch (static device allocations; no cudaMalloc allowed)
// ---------------------------------------------------------------------------
__device__ float g_normed[T * C];
__device__ float g_qkv[T * 3 * C];
__device__ float g_attn[T * C];
__device__ float g_x1[T * C];
__device__ float g_weff[C * C];
__device__ float g_beff[C];
__device__ float g_hL[TH * HID];
__device__ float g_pre[3 * TH * HID];
// tf32-rounded weight copies (producers round; GEMM loads raw via cp.async)
__device__ float g_wqkv_r[C * 3 * C];
__device__ float g_wproj_r[C * C];
__device__ float g_wfc1_r[C * HID];
__device__ float g_wfc2_r[HID * C];

// ---------------------------------------------------------------------------
// Helpers
// ---------------------------------------------------------------------------
__device__ __forceinline__ float to_tf32(float x) {
    float r;
    asm("cvt.rna.tf32.f32 %0, %1;" : "=f"(r) : "f"(x));
    return r;
}
__device__ __forceinline__ float gelu_exact(float v) {
    return 0.5f * v * (1.0f + erff(v * 0.70710678118654752f));
}
__device__ __forceinline__ uint32_t smem_u32(const void* p) {
    uint32_t a;
    asm("{ .reg .u64 t; cvta.to.shared.u64 t, %1; cvt.u32.u64 %0, t; }"
        : "=r"(a) : "l"(p));
    return a;
}
__device__ __forceinline__ void cp_async16(uint32_t dst, const void* src, int srcbytes) {
    asm volatile("cp.async.cg.shared.global [%0], [%1], 16, %2;"
                 :: "r"(dst), "l"(src), "r"(srcbytes));
}
#define CP_COMMIT() asm volatile("cp.async.commit_group;" ::: "memory")
#define CP_WAIT1()  asm volatile("cp.async.wait_group 1;" ::: "memory")

// mma.sync m16n8k8 tf32: D(4f) = A(4r) * B(2r) + D
__device__ __forceinline__ void mma_tf32(float* c, const uint32_t* a, const uint32_t* b) {
    asm volatile(
        "mma.sync.aligned.m16n8k8.row.col.f32.tf32.tf32.f32 "
        "{%0,%1,%2,%3}, {%4,%5,%6,%7}, {%8,%9}, {%0,%1,%2,%3};"
        : "+f"(c[0]), "+f"(c[1]), "+f"(c[2]), "+f"(c[3])
        : "r"(a[0]), "r"(a[1]), "r"(a[2]), "r"(a[3]), "r"(b[0]), "r"(b[1]));
}

// single extern shared symbol shared by all kernels
extern __shared__ char dsmem[];

// smem GEMM layout (floats)
#define APITCH 36
#define BPITCH 136
#define ASZ (128 * APITCH)          // 4608 floats
#define BSZ (32 * BPITCH)           // 4352 floats
#define STG_F (ASZ + BSZ)           // 8960 floats per stage
#define STAGES 3
#define GEMM_SMEM (STAGES * STG_F * 4)   // 107520 bytes

// ---------------------------------------------------------------------------
// tf32 tensor-core GEMM: C[128m x 128n] tile per CTA, BK=32, 3-stage cp.async.
// All A/B operands must be pre-rounded to tf32 by their producers.
// Epilogue: v = alpha*(acc + bias[c]); v += Cin; v += resid; optional GELU
// (GELU output is tf32-rounded since it feeds a later GEMM).
// N, K multiples of 128 / 32 at every call site; M guarded.
// ---------------------------------------------------------------------------
__global__ void __launch_bounds__(256, 2) tgemm_k(
    const float* __restrict__ A, int lda,
    const float* __restrict__ B, int ldb,
    float* __restrict__ Cc, int ldc,
    const float* __restrict__ Cin, int ldcin,
    const float* __restrict__ bias,
    const float* __restrict__ resid, int ldr,
    int M, int K,
    const float* __restrict__ alpha_ptr, int aidx,
    int do_gelu)
{
    const int tid = threadIdx.x;
    const int wid = tid >> 5, lid = tid & 31;
    const int warpM = wid >> 2;          // 0..1  (64 rows each)
    const int warpN = wid & 3;           // 0..3  (32 cols each)
    const int lq = lid >> 2;             // 0..7
    const int lr = lid & 3;              // 0..3
    const int bn = blockIdx.x, bm = blockIdx.y;

    const uint32_t sbase = smem_u32(dsmem);

    // per-thread load coords (4 x 16B for A, 4 x 16B for B per chunk)
    const int aRow0 = tid >> 3;          // +64*u
    const int aC4   = (tid & 7) * 4;
    const int bK0   = tid >> 5;          // +8*u
    const int bN4   = (tid & 31) * 4;

    float acc[4][4][4];
    #pragma unroll
    for (int mi = 0; mi < 4; mi++)
        #pragma unroll
        for (int ni = 0; ni < 4; ni++)
            #pragma unroll
            for (int j = 0; j < 4; j++) acc[mi][ni][j] = 0.f;

    const int nch = K >> 5;

    auto issue = [&](int ci, int st) {
        int k0 = ci << 5;
        uint32_t aBase = sbase + (uint32_t)st * (STG_F * 4);
        uint32_t bBase = aBase + ASZ * 4;
        #pragma unroll
        for (int u = 0; u < 4; u++) {
            int row = aRow0 + u * 32;
            int r = bm * 128 + row;
            bool ok = (r < M);
            const float* src = A + (size_t)(ok ? r : 0) * lda + k0 + aC4;
            cp_async16(aBase + (uint32_t)(row * APITCH + aC4) * 4, src, ok ? 16 : 0);
        }
        #pragma unroll
        for (int u = 0; u < 4; u++) {
            int kk = bK0 + u * 8;
            const float* src = B + (size_t)(k0 + kk) * ldb + bn * 128 + bN4;
            cp_async16(bBase + (uint32_t)(kk * BPITCH + bN4) * 4, src, 16);
        }
    };

    // prologue: stages 0..STAGES-2  (nch >= 4 always)
    #pragma unroll
    for (int s = 0; s < STAGES - 1; s++) { issue(s, s); CP_COMMIT(); }

    for (int i = 0; i < nch; i++) {
        CP_WAIT1();
        __syncthreads();

        int st = i % STAGES;
        const uint32_t* ap = (const uint32_t*)(dsmem) + (size_t)st * STG_F;
        const uint32_t* bp = ap + ASZ;

        #pragma unroll
        for (int ks = 0; ks < 4; ks++) {
            int k0 = ks << 3;
            uint32_t afr[4][4], bfr[4][2];
            #pragma unroll
            for (int mi = 0; mi < 4; mi++) {
                int m0 = warpM * 64 + mi * 16 + lq;
                afr[mi][0] = ap[m0 * APITCH + k0 + lr];
                afr[mi][1] = ap[(m0 + 8) * APITCH + k0 + lr];
                afr[mi][2] = ap[m0 * APITCH + k0 + lr + 4];
                afr[mi][3] = ap[(m0 + 8) * APITCH + k0 + lr + 4];
            }
            #pragma unroll
            for (int ni = 0; ni < 4; ni++) {
                int n0 = warpN * 32 + ni * 8 + lq;
                bfr[ni][0] = bp[(k0 + lr) * BPITCH + n0];
                bfr[ni][1] = bp[(k0 + lr + 4) * BPITCH + n0];
            }
            #pragma unroll
            for (int mi = 0; mi < 4; mi++)
                #pragma unroll
                for (int ni = 0; ni < 4; ni++)
                    mma_tf32(acc[mi][ni], afr[mi], bfr[ni]);
        }

        __syncthreads();
        int nx = i + STAGES - 1;
        if (nx < nch) issue(nx, nx % STAGES);
        CP_COMMIT();
    }

    // ---- epilogue: registers -> gmem with fused ops ----
    float alpha = alpha_ptr ? alpha_ptr[aidx] : 1.0f;
    #pragma unroll
    for (int mi = 0; mi < 4; mi++) {
        #pragma unroll
        for (int h = 0; h < 2; h++) {
            int r = bm * 128 + warpM * 64 + mi * 16 + lq + h * 8;
            if (r >= M) continue;
            #pragma unroll
            for (int ni = 0; ni < 4; ni++) {
                int cc = bn * 128 + warpN * 32 + ni * 8 + lr * 2;
                float v0 = acc[mi][ni][h * 2 + 0];
                float v1 = acc[mi][ni][h * 2 + 1];
                if (bias) { v0 += bias[cc]; v1 += bias[cc + 1]; }
                v0 *= alpha; v1 *= alpha;
                if (Cin) {
                    const float* cp = Cin + (size_t)r * ldcin + cc;
                    v0 += cp[0]; v1 += cp[1];
                }
                if (resid) {
                    const float* rp = resid + (size_t)r * ldr + cc;
                    v0 += rp[0]; v1 += rp[1];
                }
                if (do_gelu) {
                    v0 = to_tf32(gelu_exact(v0));   // feeds next GEMM
                    v1 = to_tf32(gelu_exact(v1));
                }
                float2* op = (float2*)(Cc + (size_t)r * ldc + cc);
                *op = make_float2(v0, v1);
            }
        }
    }
}

// ---------------------------------------------------------------------------
// LayerNorm (tf32-rounded output; feeds GEMMs only)
// ---------------------------------------------------------------------------
__global__ __launch_bounds__(256) void ln_kernel(
    const float* __restrict__ x,
    const float* __restrict__ gl, const float* __restrict__ bl,
    const float* __restrict__ gs, const float* __restrict__ bs,
    float* __restrict__ out)
{
    int row = blockIdx.x;
    const float* xr = x + (size_t)row * C;
    int t = threadIdx.x;
    float v0 = xr[t], v1 = xr[t + 256], v2 = xr[t + 512];
    float s = v0 + v1 + v2;
    float ss = v0 * v0 + v1 * v1 + v2 * v2;
    #pragma unroll
    for (int o = 16; o; o >>= 1) {
        s  += __shfl_xor_sync(0xffffffffu, s, o);
        ss += __shfl_xor_sync(0xffffffffu, ss, o);
    }
    __shared__ float sm[2][8];
    int warp = t >> 5, lane = t & 31;
    if (!lane) { sm[0][warp] = s; sm[1][warp] = ss; }
    __syncthreads();
    if (t < 32) {
        float a = (lane < 8) ? sm[0][lane] : 0.f;
        float b = (lane < 8) ? sm[1][lane] : 0.f;
        #pragma unroll
        for (int o = 4; o; o >>= 1) {
            a += __shfl_xor_sync(0xffffffffu, a, o);
            b += __shfl_xor_sync(0xffffffffu, b, o);
        }
        if (!lane) { sm[0][0] = a; sm[1][0] = b; }
    }
    __syncthreads();
    float mean = sm[0][0] * (1.0f / C);
    float var  = sm[1][0] * (1.0f / C) - mean * mean;
    float rstd = rsqrtf(var + 1e-5f);
    const float* g  = (row < TH) ? gl : gs;
    const float* bb = (row < TH) ? bl : bs;
    float* orow = out + (size_t)row * C;
    orow[t]       = to_tf32((v0 - mean) * rstd * g[t]       + bb[t]);
    orow[t + 256] = to_tf32((v1 - mean) * rstd * g[t + 256] + bb[t + 256]);
    orow[t + 512] = to_tf32((v2 - mean) * rstd * g[t + 512] + bb[t + 512]);
}

// ---------------------------------------------------------------------------
// Effective small-branch projection weight/bias (weff tf32-rounded)
// ---------------------------------------------------------------------------
__global__ void weff_kernel(const float* __restrict__ w, const float* __restrict__ b,
                            const float* __restrict__ g,
                            float* __restrict__ weff, float* __restrict__ beff)
{
    int i = blockIdx.x * blockDim.x + threadIdx.x;
    if (i < C * C) {
        int r = i / C, c = i % C;
        float m = g[0];
        if (r < 384 && c < 384) m += g[1];
        if (r < 256 && c < 256) m += g[2];
        weff[i] = to_tf32(w[i] * m);
    }
    if (i < C) {
        float m = g[0];
        if (i < 384) m += g[1];
        if (i < 256) m += g[2];
        beff[i] = b[i] * m;
    }
}

// ---------------------------------------------------------------------------
// tf32 rounding copy (for weights)
// ---------------------------------------------------------------------------
__global__ void round4_kernel(const float4* __restrict__ in, float4* __restrict__ out,
                              int n4)
{
    int i = blockIdx.x * blockDim.x + threadIdx.x;
    if (i < n4) {
        float4 v = in[i];
        v.x = to_tf32(v.x); v.y = to_tf32(v.y);
        v.z = to_tf32(v.z); v.w = to_tf32(v.w);
        out[i] = v;
    }
}

// ---------------------------------------------------------------------------
// Attention: one block per (b, h); outputs tf32-rounded (feed proj GEMM)
// ---------------------------------------------------------------------------
#define KPITCH 65
#define PSTRIDE 264

__global__ __launch_bounds__(256) void attn_kernel(
    const float* __restrict__ qkv, float* __restrict__ out)
{
    int bh = blockIdx.x;
    int b = bh / NH, h = bh % NH;
    float* smemf = (float*)dsmem;
    float* Ksh = smemf;
    float* Vsh = Ksh + NTOK * KPITCH;
    float* Psh = Vsh + NTOK * KPITCH;
    float* Qsh = Psh + 8 * PSTRIDE;

    int tid = threadIdx.x, warp = tid >> 5, lane = tid & 31;
    const float* base = qkv + (size_t)b * NTOK * (3 * C);

    for (int idx = tid; idx < NTOK * HD; idx += 256) {
        int m = idx / HD, d = idx % HD;
        const float* row = base + (size_t)m * (3 * C) + h * HD + d;
        Ksh[m * KPITCH + d] = row[C];
        Vsh[m * KPITCH + d] = row[2 * C];
    }
    __syncthreads();

    float* myP = Psh + warp * PSTRIDE;
    float* myQ = Qsh + warp * HD;

    for (int n = warp; n < NTOK; n += 8) {
        const float* qrow = base + (size_t)n * (3 * C) + h * HD;
        myQ[lane]      = qrow[lane];
        myQ[lane + 32] = qrow[lane + 32];
        __syncwarp();

        float lmax = -1e30f;
        for (int m = lane; m < NTOK; m += 32) {
            const float* kr = &Ksh[m * KPITCH];
            float s0 = 0.f, s1 = 0.f, s2 = 0.f, s3 = 0.f;
            #pragma unroll
            for (int d = 0; d < HD; d += 4) {
                s0 += myQ[d]     * kr[d];
                s1 += myQ[d + 1] * kr[d + 1];
                s2 += myQ[d + 2] * kr[d + 2];
                s3 += myQ[d + 3] * kr[d + 3];
            }
            float s = ((s0 + s1) + (s2 + s3)) * 0.125f;
            myP[m] = s;
            lmax = fmaxf(lmax, s);
        }
        #pragma unroll
        for (int o = 16; o; o >>= 1)
            lmax = fmaxf(lmax, __shfl_xor_sync(0xffffffffu, lmax, o));

        float lsum = 0.f;
        for (int m = lane; m < NTOK; m += 32) {
            float p = expf(myP[m] - lmax);
            myP[m] = p;
            lsum += p;
        }
        #pragma unroll
        for (int o = 16; o; o >>= 1)
            lsum += __shfl_xor_sync(0xffffffffu, lsum, o);
        __syncwarp();

        float a0[4] = {0.f, 0.f, 0.f, 0.f};
        float a1[4] = {0.f, 0.f, 0.f, 0.f};
        int m = 0;
        for (; m + 4 <= NTOK; m += 4) {
            #pragma unroll
            for (int u = 0; u < 4; u++) {
                float p = myP[m + u];
                a0[u] += p * Vsh[(m + u) * KPITCH + lane];
                a1[u] += p * Vsh[(m + u) * KPITCH + 32 + lane];
            }
        }
        for (; m < NTOK; m++) {
            float p = myP[m];
            a0[0] += p * Vsh[m * KPITCH + lane];
            a1[0] += p * Vsh[m * KPITCH + 32 + lane];
        }
        float inv = 1.0f / lsum;
        float o0 = (a0[0] + a0[1] + a0[2] + a0[3]) * inv;
        float o1 = (a1[0] + a1[1] + a1[2] + a1[3]) * inv;

        float* orow = out + ((size_t)b * NTOK + n) * C + h * HD;
        orow[lane]      = to_tf32(o0);
        orow[lane + 32] = to_tf32(o1);
        __syncwarp();
    }
}

// ---------------------------------------------------------------------------
// Exact GELU elementwise (vectorized, tf32-rounded: feeds FC2 GEMMs)
// ---------------------------------------------------------------------------
__global__ void gelu4_kernel(float4* __restrict__ p, int n4)
{
    int i = blockIdx.x * blockDim.x + threadIdx.x;
    if (i < n4) {
        float4 v = p[i];
        v.x = to_tf32(gelu_exact(v.x)); v.y = to_tf32(gelu_exact(v.y));
        v.z = to_tf32(gelu_exact(v.z)); v.w = to_tf32(gelu_exact(v.w));
        p[i] = v;
    }
}

// ---------------------------------------------------------------------------
// Launch
// ---------------------------------------------------------------------------
static inline float* sym(const void* symbol) {
    void* p = nullptr;
    cudaGetSymbolAddress(&p, symbol);
    return (float*)p;
}

extern "C" void kernel_launch(void* const* d_in, const int* in_sizes, int n_in,
                              void* d_out, int out_size)
{
    const float* x      = (const float*)d_in[0];
    const float* gw     = (const float*)d_in[1];
    const float* n1l_g  = (const float*)d_in[2];
    const float* n1l_b  = (const float*)d_in[3];
    const float* n1s_g  = (const float*)d_in[4];
    const float* n1s_b  = (const float*)d_in[5];
    const float* w_qkv  = (const float*)d_in[6];
    const float* w_proj = (const float*)d_in[7];
    const float* b_proj = (const float*)d_in[8];
    const float* n2l_g  = (const float*)d_in[9];
    const float* n2l_b  = (const float*)d_in[10];
    const float* n2s_g  = (const float*)d_in[11];
    const float* n2s_b  = (const float*)d_in[12];
    const float* w_fc1  = (const float*)d_in[13];
    const float* b_fc1  = (const float*)d_in[14];
    const float* w_fc2  = (const float*)d_in[15];
    const float* b_fc2  = (const float*)d_in[16];
    float* out = (float*)d_out;

    float* normed = sym(g_normed);
    float* qkv    = sym(g_qkv);
    float* attn   = sym(g_attn);
    float* x1     = sym(g_x1);
    float* weff   = sym(g_weff);
    float* beff   = sym(g_beff);
    float* hL     = sym(g_hL);
    float* pre    = sym(g_pre);
    float* wqkv_r = sym(g_wqkv_r);
    float* wproj_r= sym(g_wproj_r);
    float* wfc1_r = sym(g_wfc1_r);
    float* wfc2_r = sym(g_wfc2_r);
    float* pre1 = pre;                        // full-K pre-act  (alpha g0)
    float* pre2 = pre + (size_t)TH * HID;     // K<=384          (alpha g1)
    float* pre3 = pre + (size_t)2 * TH * HID; // K<=256          (alpha g2)

    const int attn_smem = (2 * NTOK * KPITCH + 8 * PSTRIDE + 8 * HD) * sizeof(float);
    cudaFuncSetAttribute(attn_kernel, cudaFuncAttributeMaxDynamicSharedMemorySize,
                         attn_smem);
    cudaFuncSetAttribute(tgemm_k, cudaFuncAttributeMaxDynamicSharedMemorySize,
                         GEMM_SMEM);

    const int MB_T  = (T  + 127) / 128;   // 129
    const int MB_TH = (TH + 127) / 128;   // 65

    // 0. tf32-rounded weight copies
    round4_kernel<<<(C * 3 * C / 4 + 255) / 256, 256>>>(
        (const float4*)w_qkv, (float4*)wqkv_r, C * 3 * C / 4);
    round4_kernel<<<(C * C / 4 + 255) / 256, 256>>>(
        (const float4*)w_proj, (float4*)wproj_r, C * C / 4);
    round4_kernel<<<(C * HID / 4 + 255) / 256, 256>>>(
        (const float4*)w_fc1, (float4*)wfc1_r, C * HID / 4);
    round4_kernel<<<(HID * C / 4 + 255) / 256, 256>>>(
        (const float4*)w_fc2, (float4*)wfc2_r, HID * C / 4);

    // 1. LN1 over all tokens
    ln_kernel<<<T, 256>>>(x, n1l_g, n1l_b, n1s_g, n1s_b, normed);

    // 2. Effective small-branch projection weights
    weff_kernel<<<(C * C + 255) / 256, 256>>>(w_proj, b_proj, gw, weff, beff);

    // 3. QKV: (T x 768) @ (768 x 2304)
    tgemm_k<<<dim3(2304 / 128, MB_T), 256, GEMM_SMEM>>>(
        normed, C, wqkv_r, 3 * C, qkv, 3 * C,
        nullptr, 0, nullptr, nullptr, 0, T, C, nullptr, 0, 0);

    // 4. Attention per (b,h)
    attn_kernel<<<BATCH * NH, 256, attn_smem>>>(qkv, attn);

    // 5. Projection + residual (large: w_proj; small: folded W_eff)
    tgemm_k<<<dim3(C / 128, MB_TH), 256, GEMM_SMEM>>>(
        attn, C, wproj_r, C, x1, C,
        nullptr, 0, b_proj, x, C, TH, C, nullptr, 0, 0);
    tgemm_k<<<dim3(C / 128, MB_TH), 256, GEMM_SMEM>>>(
        attn + (size_t)TH * C, C, weff, C, x1 + (size_t)TH * C, C,
        nullptr, 0, beff, x + (size_t)TH * C, C, TH, C, nullptr, 0, 0);

    // 6. LN2
    ln_kernel<<<T, 256>>>(x1, n2l_g, n2l_b, n2s_g, n2s_b, normed);

    // 7. FC1
    tgemm_k<<<dim3(HID / 128, MB_TH), 256, GEMM_SMEM>>>(
        normed, C, wfc1_r, HID, hL, HID,
        nullptr, 0, b_fc1, nullptr, 0, TH, C, nullptr, 0, 1);
    const float* ns2 = normed + (size_t)TH * C;
    // small partial-K chain: pre3 (K=256) -> pre2 (+K 256:384) -> pre1 (+K 384:768, fused gelu)
    tgemm_k<<<dim3(HID / 128, MB_TH), 256, GEMM_SMEM>>>(
        ns2, C, wfc1_r, HID, pre3, HID,
        nullptr, 0, b_fc1, nullptr, 0, TH, 256, nullptr, 0, 0);
    tgemm_k<<<dim3(HID / 128, MB_TH), 256, GEMM_SMEM>>>(
        ns2 + 256, C, wfc1_r + (size_t)256 * HID, HID, pre2, HID,
        pre3, HID, nullptr, nullptr, 0, TH, 128, nullptr, 0, 0);
    tgemm_k<<<dim3(HID / 128, MB_TH), 256, GEMM_SMEM>>>(
        ns2 + 384, C, wfc1_r + (size_t)384 * HID, HID, pre1, HID,
        pre2, HID, nullptr, nullptr, 0, TH, 384, nullptr, 0, 1);
    // gelu pre2 & pre3 (pre1 already gelu'd in epilogue)
    {
        int n4 = (2 * TH * HID) / 4;
        gelu4_kernel<<<(n4 + 255) / 256, 256>>>((float4*)pre2, n4);
    }

    // 8. FC2
    tgemm_k<<<dim3(C / 128, MB_TH), 256, GEMM_SMEM>>>(
        hL, HID, wfc2_r, C, out, C,
        nullptr, 0, b_fc2, x1, C, TH, HID, nullptr, 0, 0);
    float* outS = out + (size_t)TH * C;
    const float* x1S = x1 + (size_t)TH * C;
    tgemm_k<<<dim3(C / 128, MB_TH), 256, GEMM_SMEM>>>(
        pre1, HID, wfc2_r, C, outS, C,
        nullptr, 0, b_fc2, x1S, C, TH, HID, gw, 0, 0);
    tgemm_k<<<dim3(384 / 128, MB_TH), 256, GEMM_SMEM>>>(
        pre2, HID, wfc2_r, C, outS, C,
        outS, C, b_fc2, nullptr, 0, TH, HID, gw, 1, 0);
    tgemm_k<<<dim3(256 / 128, MB_TH), 256, GEMM_SMEM>>>(
        pre3, HID, wfc2_r, C, outS, C,
        outS, C, b_fc2, nullptr, 0, TH, HID, gw, 2, 0);
}

// round 12
// speedup vs baseline: 4.5830x; 1.0728x over previous
#include <cuda_runtime.h>
#include <cuda_bf16.h>
#include <math.h>
#include <stdint.h>

// ---------------------------------------------------------------------------
// Problem constants
// ---------------------------------------------------------------------------
#define BATCH   64
#define B2      32
#define NTOK    257
#define C       768
#define HID     3072
#define NH      12
#define HD      64
#define T       (BATCH * NTOK)      // 16448 tokens total
#define TH      (B2 * NTOK)         // 8224 tokens per half

// ---------------------------------------------------------------------------
// Scratch (static device allocations; no cudaMalloc allowed)
// ---------------------------------------------------------------------------
__device__ float g_normed[T * C];
__device__ float g_qkv[T * 3 * C];
__device__ float g_attn[T * C];
__device__ float g_x1[T * C];
__device__ float g_weff[C * C];
__device__ float g_beff[C];
__device__ float g_hL[TH * HID];
__device__ float g_pre[3 * TH * HID];
// tf32-rounded weight copies (producers round; GEMM loads raw via cp.async)
__device__ float g_wqkv_r[C * 3 * C];
__device__ float g_wproj_r[C * C];
__device__ float g_wfc1_r[C * HID];
__device__ float g_wfc2_r[HID * C];

// ---------------------------------------------------------------------------
// Helpers
// ---------------------------------------------------------------------------
__device__ __forceinline__ float to_tf32(float x) {
    float r;
    asm("cvt.rna.tf32.f32 %0, %1;" : "=f"(r) : "f"(x));
    return r;
}
__device__ __forceinline__ float gelu_exact(float v) {
    return 0.5f * v * (1.0f + erff(v * 0.70710678118654752f));
}
__device__ __forceinline__ uint32_t smem_u32(const void* p) {
    uint32_t a;
    asm("{ .reg .u64 t; cvta.to.shared.u64 t, %1; cvt.u32.u64 %0, t; }"
        : "=r"(a) : "l"(p));
    return a;
}
__device__ __forceinline__ void cp_async16(uint32_t dst, const void* src, int srcbytes) {
    asm volatile("cp.async.cg.shared.global [%0], [%1], 16, %2;"
                 :: "r"(dst), "l"(src), "r"(srcbytes));
}
#define CP_COMMIT() asm volatile("cp.async.commit_group;" ::: "memory")
#define CP_WAIT1()  asm volatile("cp.async.wait_group 1;" ::: "memory")

// mma.sync m16n8k8 tf32: D(4f) = A(4r) * B(2r) + D
__device__ __forceinline__ void mma_tf32(float* c, const uint32_t* a, const uint32_t* b) {
    asm volatile(
        "mma.sync.aligned.m16n8k8.row.col.f32.tf32.tf32.f32 "
        "{%0,%1,%2,%3}, {%4,%5,%6,%7}, {%8,%9}, {%0,%1,%2,%3};"
        : "+f"(c[0]), "+f"(c[1]), "+f"(c[2]), "+f"(c[3])
        : "r"(a[0]), "r"(a[1]), "r"(a[2]), "r"(a[3]), "r"(b[0]), "r"(b[1]));
}

// single extern shared symbol shared by all kernels
extern __shared__ char dsmem[];

// smem GEMM layout (floats)
#define APITCH 36
#define BPITCH 136
#define ASZ (128 * APITCH)          // 4608 floats
#define BSZ (32 * BPITCH)           // 4352 floats
#define STG_F (ASZ + BSZ)           // 8960 floats per stage
#define STAGES 3
#define GEMM_SMEM (STAGES * STG_F * 4)   // 107520 bytes

// ---------------------------------------------------------------------------
// tf32 tensor-core GEMM: C[128m x 128n] tile per CTA, BK=32, 3-stage cp.async.
// All A/B operands must be pre-rounded to tf32 by their producers.
// Epilogue: v = alpha*(acc + bias[c]); v += Cin; v += resid; optional GELU.
// If gback != null, tf32(gelu(Cin value)) is written back to gback (same
// indexing as Cin) — used to gelu the partial-K pre-activations in place.
// N, K multiples of 128 / 32 at every call site; M guarded.
// ---------------------------------------------------------------------------
__global__ void __launch_bounds__(256, 2) tgemm_k(
    const float* __restrict__ A, int lda,
    const float* __restrict__ B, int ldb,
    float* __restrict__ Cc, int ldc,
    const float* __restrict__ Cin, int ldcin,
    const float* __restrict__ bias,
    const float* __restrict__ resid, int ldr,
    int M, int K,
    const float* __restrict__ alpha_ptr, int aidx,
    int do_gelu,
    float* __restrict__ gback)
{
    const int tid = threadIdx.x;
    const int wid = tid >> 5, lid = tid & 31;
    const int warpM = wid >> 2;          // 0..1  (64 rows each)
    const int warpN = wid & 3;           // 0..3  (32 cols each)
    const int lq = lid >> 2;             // 0..7
    const int lr = lid & 3;              // 0..3
    const int bn = blockIdx.x, bm = blockIdx.y;

    const uint32_t sbase = smem_u32(dsmem);

    // per-thread load coords (4 x 16B for A, 4 x 16B for B per chunk)
    const int aRow0 = tid >> 3;          // +32*u
    const int aC4   = (tid & 7) * 4;
    const int bK0   = tid >> 5;          // +8*u
    const int bN4   = (tid & 31) * 4;

    float acc[4][4][4];
    #pragma unroll
    for (int mi = 0; mi < 4; mi++)
        #pragma unroll
        for (int ni = 0; ni < 4; ni++)
            #pragma unroll
            for (int j = 0; j < 4; j++) acc[mi][ni][j] = 0.f;

    const int nch = K >> 5;

    auto issue = [&](int ci, int st) {
        int k0 = ci << 5;
        uint32_t aBase = sbase + (uint32_t)st * (STG_F * 4);
        uint32_t bBase = aBase + ASZ * 4;
        #pragma unroll
        for (int u = 0; u < 4; u++) {
            int row = aRow0 + u * 32;
            int r = bm * 128 + row;
            bool ok = (r < M);
            const float* src = A + (size_t)(ok ? r : 0) * lda + k0 + aC4;
            cp_async16(aBase + (uint32_t)(row * APITCH + aC4) * 4, src, ok ? 16 : 0);
        }
        #pragma unroll
        for (int u = 0; u < 4; u++) {
            int kk = bK0 + u * 8;
            const float* src = B + (size_t)(k0 + kk) * ldb + bn * 128 + bN4;
            cp_async16(bBase + (uint32_t)(kk * BPITCH + bN4) * 4, src, 16);
        }
    };

    // prologue: stages 0..STAGES-2  (nch >= 4 always)
    #pragma unroll
    for (int s = 0; s < STAGES - 1; s++) { issue(s, s); CP_COMMIT(); }

    for (int i = 0; i < nch; i++) {
        CP_WAIT1();
        __syncthreads();
        // prefetch chunk i+2 into the stage last read at iter i-1 (all warps
        // are provably past it thanks to the barrier above)
        int nx = i + STAGES - 1;
        if (nx < nch) issue(nx, nx % STAGES);
        CP_COMMIT();

        int st = i % STAGES;
        const uint32_t* ap = (const uint32_t*)(dsmem) + (size_t)st * STG_F;
        const uint32_t* bp = ap + ASZ;

        #pragma unroll
        for (int ks = 0; ks < 4; ks++) {
            int k0 = ks << 3;
            uint32_t afr[4][4], bfr[4][2];
            #pragma unroll
            for (int mi = 0; mi < 4; mi++) {
                int m0 = warpM * 64 + mi * 16 + lq;
                afr[mi][0] = ap[m0 * APITCH + k0 + lr];
                afr[mi][1] = ap[(m0 + 8) * APITCH + k0 + lr];
                afr[mi][2] = ap[m0 * APITCH + k0 + lr + 4];
                afr[mi][3] = ap[(m0 + 8) * APITCH + k0 + lr + 4];
            }
            #pragma unroll
            for (int ni = 0; ni < 4; ni++) {
                int n0 = warpN * 32 + ni * 8 + lq;
                bfr[ni][0] = bp[(k0 + lr) * BPITCH + n0];
                bfr[ni][1] = bp[(k0 + lr + 4) * BPITCH + n0];
            }
            #pragma unroll
            for (int mi = 0; mi < 4; mi++)
                #pragma unroll
                for (int ni = 0; ni < 4; ni++)
                    mma_tf32(acc[mi][ni], afr[mi], bfr[ni]);
        }
        // no trailing barrier: next iteration's top barrier provides it
    }

    // ---- epilogue: registers -> gmem with fused ops ----
    float alpha = alpha_ptr ? alpha_ptr[aidx] : 1.0f;
    #pragma unroll
    for (int mi = 0; mi < 4; mi++) {
        #pragma unroll
        for (int h = 0; h < 2; h++) {
            int r = bm * 128 + warpM * 64 + mi * 16 + lq + h * 8;
            if (r >= M) continue;
            #pragma unroll
            for (int ni = 0; ni < 4; ni++) {
                int cc = bn * 128 + warpN * 32 + ni * 8 + lr * 2;
                float v0 = acc[mi][ni][h * 2 + 0];
                float v1 = acc[mi][ni][h * 2 + 1];
                if (bias) { v0 += bias[cc]; v1 += bias[cc + 1]; }
                v0 *= alpha; v1 *= alpha;
                if (Cin) {
                    const float* cp = Cin + (size_t)r * ldcin + cc;
                    float c0 = cp[0], c1 = cp[1];
                    v0 += c0; v1 += c1;
                    if (gback) {
                        float2* gp = (float2*)(gback + (size_t)r * ldcin + cc);
                        *gp = make_float2(to_tf32(gelu_exact(c0)),
                                          to_tf32(gelu_exact(c1)));
                    }
                }
                if (resid) {
                    const float* rp = resid + (size_t)r * ldr + cc;
                    v0 += rp[0]; v1 += rp[1];
                }
                if (do_gelu) {
                    v0 = to_tf32(gelu_exact(v0));   // feeds next GEMM
                    v1 = to_tf32(gelu_exact(v1));
                }
                float2* op = (float2*)(Cc + (size_t)r * ldc + cc);
                *op = make_float2(v0, v1);
            }
        }
    }
}

// ---------------------------------------------------------------------------
// LayerNorm (tf32-rounded output; feeds GEMMs only)
// ---------------------------------------------------------------------------
__global__ __launch_bounds__(256) void ln_kernel(
    const float* __restrict__ x,
    const float* __restrict__ gl, const float* __restrict__ bl,
    const float* __restrict__ gs, const float* __restrict__ bs,
    float* __restrict__ out)
{
    int row = blockIdx.x;
    const float* xr = x + (size_t)row * C;
    int t = threadIdx.x;
    float v0 = xr[t], v1 = xr[t + 256], v2 = xr[t + 512];
    float s = v0 + v1 + v2;
    float ss = v0 * v0 + v1 * v1 + v2 * v2;
    #pragma unroll
    for (int o = 16; o; o >>= 1) {
        s  += __shfl_xor_sync(0xffffffffu, s, o);
        ss += __shfl_xor_sync(0xffffffffu, ss, o);
    }
    __shared__ float sm[2][8];
    int warp = t >> 5, lane = t & 31;
    if (!lane) { sm[0][warp] = s; sm[1][warp] = ss; }
    __syncthreads();
    if (t < 32) {
        float a = (lane < 8) ? sm[0][lane] : 0.f;
        float b = (lane < 8) ? sm[1][lane] : 0.f;
        #pragma unroll
        for (int o = 4; o; o >>= 1) {
            a += __shfl_xor_sync(0xffffffffu, a, o);
            b += __shfl_xor_sync(0xffffffffu, b, o);
        }
        if (!lane) { sm[0][0] = a; sm[1][0] = b; }
    }
    __syncthreads();
    float mean = sm[0][0] * (1.0f / C);
    float var  = sm[1][0] * (1.0f / C) - mean * mean;
    float rstd = rsqrtf(var + 1e-5f);
    const float* g  = (row < TH) ? gl : gs;
    const float* bb = (row < TH) ? bl : bs;
    float* orow = out + (size_t)row * C;
    orow[t]       = to_tf32((v0 - mean) * rstd * g[t]       + bb[t]);
    orow[t + 256] = to_tf32((v1 - mean) * rstd * g[t + 256] + bb[t + 256]);
    orow[t + 512] = to_tf32((v2 - mean) * rstd * g[t + 512] + bb[t + 512]);
}

// ---------------------------------------------------------------------------
// Effective small-branch projection weight/bias (weff tf32-rounded)
// ---------------------------------------------------------------------------
__global__ void weff_kernel(const float* __restrict__ w, const float* __restrict__ b,
                            const float* __restrict__ g,
                            float* __restrict__ weff, float* __restrict__ beff)
{
    int i = blockIdx.x * blockDim.x + threadIdx.x;
    if (i < C * C) {
        int r = i / C, c = i % C;
        float m = g[0];
        if (r < 384 && c < 384) m += g[1];
        if (r < 256 && c < 256) m += g[2];
        weff[i] = to_tf32(w[i] * m);
    }
    if (i < C) {
        float m = g[0];
        if (i < 384) m += g[1];
        if (i < 256) m += g[2];
        beff[i] = b[i] * m;
    }
}

// ---------------------------------------------------------------------------
// tf32 rounding copy (for weights)
// ---------------------------------------------------------------------------
__global__ void round4_kernel(const float4* __restrict__ in, float4* __restrict__ out,
                              int n4)
{
    int i = blockIdx.x * blockDim.x + threadIdx.x;
    if (i < n4) {
        float4 v = in[i];
        v.x = to_tf32(v.x); v.y = to_tf32(v.y);
        v.z = to_tf32(v.z); v.w = to_tf32(v.w);
        out[i] = v;
    }
}

// ---------------------------------------------------------------------------
// Attention: one block per (b, h); K fp32 in smem, V packed bf16x2 in smem
// (halves V smem + PV smem reads -> 111KB total -> 2 blocks/SM).
// Output tf32-rounded (feeds proj GEMM).
// ---------------------------------------------------------------------------
#define KPITCH 65
#define VPITCH 33
#define PSTRIDE 258

__global__ __launch_bounds__(256) void attn_kernel(
    const float* __restrict__ qkv, float* __restrict__ out)
{
    int bh = blockIdx.x;
    int b = bh / NH, h = bh % NH;
    float* smemf = (float*)dsmem;
    float*    Ksh = smemf;                               // 257*65 f
    uint32_t* Vp  = (uint32_t*)(Ksh + NTOK * KPITCH);    // 257*33 u32
    float*    Psh = (float*)(Vp + NTOK * VPITCH);        // 8*258 f
    float*    Qsh = Psh + 8 * PSTRIDE;                   // 8*64 f

    int tid = threadIdx.x, warp = tid >> 5, lane = tid & 31;
    const float* base = qkv + (size_t)b * NTOK * (3 * C);

    // K (fp32) and V (bf16x2 packed: word d holds (V[d], V[d+32]))
    for (int idx = tid; idx < NTOK * HD; idx += 256) {
        int m = idx / HD, d = idx % HD;
        Ksh[m * KPITCH + d] = base[(size_t)m * (3 * C) + h * HD + d + C];
    }
    for (int idx = tid; idx < NTOK * 32; idx += 256) {
        int m = idx >> 5, d = idx & 31;
        const float* vrow = base + (size_t)m * (3 * C) + h * HD + 2 * C;
        __nv_bfloat162 p2 = __floats2bfloat162_rn(vrow[d], vrow[d + 32]);
        Vp[m * VPITCH + d] = *(uint32_t*)&p2;
    }
    __syncthreads();

    float* myP = Psh + warp * PSTRIDE;
    float* myQ = Qsh + warp * HD;

    for (int n = warp; n < NTOK; n += 8) {
        const float* qrow = base + (size_t)n * (3 * C) + h * HD;
        myQ[lane]      = qrow[lane];
        myQ[lane + 32] = qrow[lane + 32];
        __syncwarp();

        float lmax = -1e30f;
        for (int m = lane; m < NTOK; m += 32) {
            const float* kr = &Ksh[m * KPITCH];
            float s0 = 0.f, s1 = 0.f, s2 = 0.f, s3 = 0.f;
            #pragma unroll
            for (int d = 0; d < HD; d += 4) {
                s0 += myQ[d]     * kr[d];
                s1 += myQ[d + 1] * kr[d + 1];
                s2 += myQ[d + 2] * kr[d + 2];
                s3 += myQ[d + 3] * kr[d + 3];
            }
            float s = ((s0 + s1) + (s2 + s3)) * 0.125f;
            myP[m] = s;
            lmax = fmaxf(lmax, s);
        }
        #pragma unroll
        for (int o = 16; o; o >>= 1)
            lmax = fmaxf(lmax, __shfl_xor_sync(0xffffffffu, lmax, o));

        float lsum = 0.f;
        for (int m = lane; m < NTOK; m += 32) {
            float p = expf(myP[m] - lmax);
            myP[m] = p;
            lsum += p;
        }
        #pragma unroll
        for (int o = 16; o; o >>= 1)
            lsum += __shfl_xor_sync(0xffffffffu, lsum, o);
        __syncwarp();

        float a0[4] = {0.f, 0.f, 0.f, 0.f};
        float a1[4] = {0.f, 0.f, 0.f, 0.f};
        int m = 0;
        for (; m + 4 <= NTOK; m += 4) {
            #pragma unroll
            for (int u = 0; u < 4; u++) {
                float p = myP[m + u];
                uint32_t w = Vp[(m + u) * VPITCH + lane];
                a0[u] += p * __uint_as_float(w << 16);
                a1[u] += p * __uint_as_float(w & 0xFFFF0000u);
            }
        }
        for (; m < NTOK; m++) {
            float p = myP[m];
            uint32_t w = Vp[m * VPITCH + lane];
            a0[0] += p * __uint_as_float(w << 16);
            a1[0] += p * __uint_as_float(w & 0xFFFF0000u);
        }
        float inv = 1.0f / lsum;
        float o0 = (a0[0] + a0[1] + a0[2] + a0[3]) * inv;
        float o1 = (a1[0] + a1[1] + a1[2] + a1[3]) * inv;

        float* orow = out + ((size_t)b * NTOK + n) * C + h * HD;
        orow[lane]      = to_tf32(o0);
        orow[lane + 32] = to_tf32(o1);
        __syncwarp();
    }
}

// ---------------------------------------------------------------------------
// Launch
// ---------------------------------------------------------------------------
static inline float* sym(const void* symbol) {
    void* p = nullptr;
    cudaGetSymbolAddress(&p, symbol);
    return (float*)p;
}

extern "C" void kernel_launch(void* const* d_in, const int* in_sizes, int n_in,
                              void* d_out, int out_size)
{
    const float* x      = (const float*)d_in[0];
    const float* gw     = (const float*)d_in[1];
    const float* n1l_g  = (const float*)d_in[2];
    const float* n1l_b  = (const float*)d_in[3];
    const float* n1s_g  = (const float*)d_in[4];
    const float* n1s_b  = (const float*)d_in[5];
    const float* w_qkv  = (const float*)d_in[6];
    const float* w_proj = (const float*)d_in[7];
    const float* b_proj = (const float*)d_in[8];
    const float* n2l_g  = (const float*)d_in[9];
    const float* n2l_b  = (const float*)d_in[10];
    const float* n2s_g  = (const float*)d_in[11];
    const float* n2s_b  = (const float*)d_in[12];
    const float* w_fc1  = (const float*)d_in[13];
    const float* b_fc1  = (const float*)d_in[14];
    const float* w_fc2  = (const float*)d_in[15];
    const float* b_fc2  = (const float*)d_in[16];
    float* out = (float*)d_out;

    float* normed = sym(g_normed);
    float* qkv    = sym(g_qkv);
    float* attn   = sym(g_attn);
    float* x1     = sym(g_x1);
    float* weff   = sym(g_weff);
    float* beff   = sym(g_beff);
    float* hL     = sym(g_hL);
    float* pre    = sym(g_pre);
    float* wqkv_r = sym(g_wqkv_r);
    float* wproj_r= sym(g_wproj_r);
    float* wfc1_r = sym(g_wfc1_r);
    float* wfc2_r = sym(g_wfc2_r);
    float* pre1 = pre;                        // full-K pre-act  (alpha g0)
    float* pre2 = pre + (size_t)TH * HID;     // K<=384          (alpha g1)
    float* pre3 = pre + (size_t)2 * TH * HID; // K<=256          (alpha g2)

    const int attn_smem = (NTOK * KPITCH + NTOK * VPITCH + 8 * PSTRIDE + 8 * HD) * 4;
    cudaFuncSetAttribute(attn_kernel, cudaFuncAttributeMaxDynamicSharedMemorySize,
                         attn_smem);
    cudaFuncSetAttribute(tgemm_k, cudaFuncAttributeMaxDynamicSharedMemorySize,
                         GEMM_SMEM);

    const int MB_T  = (T  + 127) / 128;   // 129
    const int MB_TH = (TH + 127) / 128;   // 65

    // 0. tf32-rounded weight copies
    round4_kernel<<<(C * 3 * C / 4 + 255) / 256, 256>>>(
        (const float4*)w_qkv, (float4*)wqkv_r, C * 3 * C / 4);
    round4_kernel<<<(C * C / 4 + 255) / 256, 256>>>(
        (const float4*)w_proj, (float4*)wproj_r, C * C / 4);
    round4_kernel<<<(C * HID / 4 + 255) / 256, 256>>>(
        (const float4*)w_fc1, (float4*)wfc1_r, C * HID / 4);
    round4_kernel<<<(HID * C / 4 + 255) / 256, 256>>>(
        (const float4*)w_fc2, (float4*)wfc2_r, HID * C / 4);

    // 1. LN1 over all tokens
    ln_kernel<<<T, 256>>>(x, n1l_g, n1l_b, n1s_g, n1s_b, normed);

    // 2. Effective small-branch projection weights
    weff_kernel<<<(C * C + 255) / 256, 256>>>(w_proj, b_proj, gw, weff, beff);

    // 3. QKV: (T x 768) @ (768 x 2304)
    tgemm_k<<<dim3(2304 / 128, MB_T), 256, GEMM_SMEM>>>(
        normed, C, wqkv_r, 3 * C, qkv, 3 * C,
        nullptr, 0, nullptr, nullptr, 0, T, C, nullptr, 0, 0, nullptr);

    // 4. Attention per (b,h)
    attn_kernel<<<BATCH * NH, 256, attn_smem>>>(qkv, attn);

    // 5. Projection + residual (large: w_proj; small: folded W_eff)
    tgemm_k<<<dim3(C / 128, MB_TH), 256, GEMM_SMEM>>>(
        attn, C, wproj_r, C, x1, C,
        nullptr, 0, b_proj, x, C, TH, C, nullptr, 0, 0, nullptr);
    tgemm_k<<<dim3(C / 128, MB_TH), 256, GEMM_SMEM>>>(
        attn + (size_t)TH * C, C, weff, C, x1 + (size_t)TH * C, C,
        nullptr, 0, beff, x + (size_t)TH * C, C, TH, C, nullptr, 0, 0, nullptr);

    // 6. LN2
    ln_kernel<<<T, 256>>>(x1, n2l_g, n2l_b, n2s_g, n2s_b, normed);

    // 7. FC1
    tgemm_k<<<dim3(HID / 128, MB_TH), 256, GEMM_SMEM>>>(
        normed, C, wfc1_r, HID, hL, HID,
        nullptr, 0, b_fc1, nullptr, 0, TH, C, nullptr, 0, 1, nullptr);
    const float* ns2 = normed + (size_t)TH * C;
    // small partial-K chain: pre3 (K=256) -> pre2 (+K 256:384, gelu-backs pre3)
    //                        -> pre1 (+K 384:768, fused gelu, gelu-backs pre2)
    tgemm_k<<<dim3(HID / 128, MB_TH), 256, GEMM_SMEM>>>(
        ns2, C, wfc1_r, HID, pre3, HID,
        nullptr, 0, b_fc1, nullptr, 0, TH, 256, nullptr, 0, 0, nullptr);
    tgemm_k<<<dim3(HID / 128, MB_TH), 256, GEMM_SMEM>>>(
        ns2 + 256, C, wfc1_r + (size_t)256 * HID, HID, pre2, HID,
        pre3, HID, nullptr, nullptr, 0, TH, 128, nullptr, 0, 0, pre3);
    tgemm_k<<<dim3(HID / 128, MB_TH), 256, GEMM_SMEM>>>(
        ns2 + 384, C, wfc1_r + (size_t)384 * HID, HID, pre1, HID,
        pre2, HID, nullptr, nullptr, 0, TH, 384, nullptr, 0, 1, pre2);

    // 8. FC2
    tgemm_k<<<dim3(C / 128, MB_TH), 256, GEMM_SMEM>>>(
        hL, HID, wfc2_r, C, out, C,
        nullptr, 0, b_fc2, x1, C, TH, HID, nullptr, 0, 0, nullptr);
    float* outS = out + (size_t)TH * C;
    const float* x1S = x1 + (size_t)TH * C;
    tgemm_k<<<dim3(C / 128, MB_TH), 256, GEMM_SMEM>>>(
        pre1, HID, wfc2_r, C, outS, C,
        nullptr, 0, b_fc2, x1S, C, TH, HID, gw, 0, 0, nullptr);
    tgemm_k<<<dim3(384 / 128, MB_TH), 256, GEMM_SMEM>>>(
        pre2, HID, wfc2_r, C, outS, C,
        outS, C, b_fc2, nullptr, 0, TH, HID, gw, 1, 0, nullptr);
    tgemm_k<<<dim3(256 / 128, MB_TH), 256, GEMM_SMEM>>>(
        pre3, HID, wfc2_r, C, outS, C,
        outS, C, b_fc2, nullptr, 0, TH, HID, gw, 2, 0, nullptr);
}

// round 13
// speedup vs baseline: 5.8104x; 1.2678x over previous
#include <cuda_runtime.h>
#include <cuda_fp16.h>
#include <math.h>
#include <stdint.h>

// ---------------------------------------------------------------------------
// Problem constants
// ---------------------------------------------------------------------------
#define BATCH   64
#define B2      32
#define NTOK    257
#define C       768
#define HID     3072
#define NH      12
#define HD      64
#define T       (BATCH * NTOK)      // 16448 tokens total
#define TH      (B2 * NTOK)         // 8224 tokens per half

// ---------------------------------------------------------------------------
// Scratch (static device allocations; no cudaMalloc allowed)
// ---------------------------------------------------------------------------
__device__ __half g_normed_h[T * C];        // LN output (half, GEMM A operand)
__device__ __half g_qkv_h[T * 3 * C];       // QKV (half)
__device__ __half g_attn_h[T * C];          // attention out (half, proj A)
__device__ float  g_x1[T * C];              // post-attention residual (fp32)
__device__ float  g_beff[C];                // effective small proj bias
__device__ __half g_hL_h[TH * HID];         // large MLP hidden, gelu'd (half)
__device__ float  g_pre2[TH * HID];         // small pre-act chain (fp32)
__device__ float  g_pre3[TH * HID];
__device__ __half g_h1h[TH * HID];          // gelu'd small hiddens (half)
__device__ __half g_h2h[TH * HID];
__device__ __half g_h3h[TH * HID];
// transposed fp16 weights: WT[n][k], k contiguous
__device__ __half g_wqkvT[3 * C * C];
__device__ __half g_wprojT[C * C];
__device__ __half g_weffT[C * C];           // gumbel-masked proj weight
__device__ __half g_wfc1T[HID * C];
__device__ __half g_wfc2T[C * HID];

// ---------------------------------------------------------------------------
// Helpers
// ---------------------------------------------------------------------------
__device__ __forceinline__ float gelu_exact(float v) {
    return 0.5f * v * (1.0f + erff(v * 0.70710678118654752f));
}
__device__ __forceinline__ uint32_t smem_u32(const void* p) {
    uint32_t a;
    asm("{ .reg .u64 t; cvta.to.shared.u64 t, %1; cvt.u32.u64 %0, t; }"
        : "=r"(a) : "l"(p));
    return a;
}
__device__ __forceinline__ void cp_async16(uint32_t dst, const void* src, int srcbytes) {
    asm volatile("cp.async.cg.shared.global [%0], [%1], 16, %2;"
                 :: "r"(dst), "l"(src), "r"(srcbytes));
}
#define CP_COMMIT() asm volatile("cp.async.commit_group;" ::: "memory")
#define CP_WAIT3()  asm volatile("cp.async.wait_group 3;" ::: "memory")

// mma.sync m16n8k16 fp16 with fp32 accum: D(4f) = A(4r) * B(2r) + D
__device__ __forceinline__ void mma_f16(float* c, const uint32_t* a, const uint32_t* b) {
    asm volatile(
        "mma.sync.aligned.m16n8k16.row.col.f32.f16.f16.f32 "
        "{%0,%1,%2,%3}, {%4,%5,%6,%7}, {%8,%9}, {%0,%1,%2,%3};"
        : "+f"(c[0]), "+f"(c[1]), "+f"(c[2]), "+f"(c[3])
        : "r"(a[0]), "r"(a[1]), "r"(a[2]), "r"(a[3]), "r"(b[0]), "r"(b[1]));
}
__device__ __forceinline__ __half2 u32_as_h2(uint32_t w) {
    return *reinterpret_cast<__half2*>(&w);
}

// single extern shared symbol shared by all kernels
extern __shared__ char dsmem[];

// GEMM smem: A tile 128 rows x 32 halves (pitch 40 halves = 80B, conflict-free),
// B tile identical. 5 stages.
#define APITCH_H 40
#define A_BYTES  (128 * APITCH_H * 2)   // 10240
#define A_WORDS  (128 * APITCH_H / 2)   // 2560 u32
#define STG_B    (2 * A_BYTES)          // 20480
#define STAGES   5
#define GEMM_SMEM (STAGES * STG_B)      // 102400

// ---------------------------------------------------------------------------
// fp16 tensor-core GEMM: C[128m x 128n] per CTA, BK=32, 5-stage cp.async.
// A: half [M][K] (lda halves). B: half WT[N][K] (ldb halves, k contiguous).
// Epilogue: v = alpha*(acc + bias[c]); v += Cin; v += resid; optional GELU;
// store fp32 or half (out_half). If gback: writes half(gelu(Cin)) to gback.
// N mult of 128, K mult of 32 (nch >= 4); M guarded.
// ---------------------------------------------------------------------------
__global__ void __launch_bounds__(256, 2) hgemm_k(
    const __half* __restrict__ A, int lda,
    const __half* __restrict__ B, int ldb,
    void* __restrict__ Cc, int ldc, int out_half,
    const float* __restrict__ Cin, int ldcin,
    const float* __restrict__ bias,
    const float* __restrict__ resid, int ldr,
    int M, int K,
    const float* __restrict__ alpha_ptr, int aidx,
    int do_gelu,
    __half* __restrict__ gback)
{
    const int tid = threadIdx.x;
    const int wid = tid >> 5, lid = tid & 31;
    const int warpM = wid >> 2;          // 0..1  (64 rows)
    const int warpN = wid & 3;           // 0..3  (32 cols)
    const int lq = lid >> 2;             // 0..7
    const int lr = lid & 3;              // 0..3
    const int bn = blockIdx.x, bm = blockIdx.y;

    const uint32_t sbase = smem_u32(dsmem);
    const int ldRow = tid >> 2;          // 0..63 (+64)
    const int ldQ   = tid & 3;           // 16B quad within 64B row

    float acc[4][4][4];
    #pragma unroll
    for (int mi = 0; mi < 4; mi++)
        #pragma unroll
        for (int ni = 0; ni < 4; ni++)
            #pragma unroll
            for (int j = 0; j < 4; j++) acc[mi][ni][j] = 0.f;

    const int nch = K >> 5;

    auto issue = [&](int ci, int st) {
        int k0 = ci << 5;
        uint32_t aB = sbase + (uint32_t)st * STG_B;
        uint32_t bB = aB + A_BYTES;
        #pragma unroll
        for (int u = 0; u < 2; u++) {
            int row = ldRow + u * 64;
            int r = bm * 128 + row;
            bool ok = (r < M);
            const __half* src = A + (size_t)(ok ? r : 0) * lda + k0 + ldQ * 8;
            cp_async16(aB + (uint32_t)(row * 80 + ldQ * 16), src, ok ? 16 : 0);
        }
        #pragma unroll
        for (int u = 0; u < 2; u++) {
            int row = ldRow + u * 64;
            const __half* src = B + (size_t)(bn * 128 + row) * ldb + k0 + ldQ * 8;
            cp_async16(bB + (uint32_t)(row * 80 + ldQ * 16), src, 16);
        }
    };

    // prologue: first STAGES-1 chunks (guarded; nch >= 4 at every call site)
    #pragma unroll
    for (int s = 0; s < STAGES - 1; s++) {
        if (s < nch) issue(s, s);
        CP_COMMIT();
    }

    for (int i = 0; i < nch; i++) {
        CP_WAIT3();
        __syncthreads();
        int nx = i + STAGES - 1;
        if (nx < nch) issue(nx, nx % STAGES);
        CP_COMMIT();

        int st = i % STAGES;
        const uint32_t* ap = (const uint32_t*)(dsmem) + (size_t)st * (STG_B / 4);
        const uint32_t* bp = ap + A_WORDS;

        #pragma unroll
        for (int ks = 0; ks < 2; ks++) {
            int kw = ks * 8;
            uint32_t afr[4][4], bfr[4][2];
            #pragma unroll
            for (int mi = 0; mi < 4; mi++) {
                int m0 = warpM * 64 + mi * 16 + lq;
                afr[mi][0] = ap[m0 * 20 + kw + lr];
                afr[mi][1] = ap[(m0 + 8) * 20 + kw + lr];
                afr[mi][2] = ap[m0 * 20 + kw + lr + 4];
                afr[mi][3] = ap[(m0 + 8) * 20 + kw + lr + 4];
            }
            #pragma unroll
            for (int ni = 0; ni < 4; ni++) {
                int n0 = warpN * 32 + ni * 8 + lq;
                bfr[ni][0] = bp[n0 * 20 + kw + lr];
                bfr[ni][1] = bp[n0 * 20 + kw + lr + 4];
            }
            #pragma unroll
            for (int mi = 0; mi < 4; mi++)
                #pragma unroll
                for (int ni = 0; ni < 4; ni++)
                    mma_f16(acc[mi][ni], afr[mi], bfr[ni]);
        }
    }

    // ---- epilogue ----
    float alpha = alpha_ptr ? alpha_ptr[aidx] : 1.0f;
    #pragma unroll
    for (int mi = 0; mi < 4; mi++) {
        #pragma unroll
        for (int h = 0; h < 2; h++) {
            int r = bm * 128 + warpM * 64 + mi * 16 + lq + h * 8;
            if (r >= M) continue;
            #pragma unroll
            for (int ni = 0; ni < 4; ni++) {
                int cc = bn * 128 + warpN * 32 + ni * 8 + lr * 2;
                float v0 = acc[mi][ni][h * 2 + 0];
                float v1 = acc[mi][ni][h * 2 + 1];
                if (bias) { v0 += bias[cc]; v1 += bias[cc + 1]; }
                v0 *= alpha; v1 *= alpha;
                if (Cin) {
                    const float* cp = Cin + (size_t)r * ldcin + cc;
                    float c0 = cp[0], c1 = cp[1];
                    v0 += c0; v1 += c1;
                    if (gback) {
                        __half2* gp = (__half2*)(gback + (size_t)r * ldcin + cc);
                        *gp = __floats2half2_rn(gelu_exact(c0), gelu_exact(c1));
                    }
                }
                if (resid) {
                    const float* rp = resid + (size_t)r * ldr + cc;
                    v0 += rp[0]; v1 += rp[1];
                }
                if (do_gelu) { v0 = gelu_exact(v0); v1 = gelu_exact(v1); }
                if (out_half) {
                    __half2* op = (__half2*)((__half*)Cc + (size_t)r * ldc + cc);
                    *op = __floats2half2_rn(v0, v1);
                } else {
                    float2* op = (float2*)((float*)Cc + (size_t)r * ldc + cc);
                    *op = make_float2(v0, v1);
                }
            }
        }
    }
}

// ---------------------------------------------------------------------------
// LayerNorm: fp32 in, half out (feeds GEMM A operands)
// ---------------------------------------------------------------------------
__global__ __launch_bounds__(256) void ln_kernel(
    const float* __restrict__ x,
    const float* __restrict__ gl, const float* __restrict__ bl,
    const float* __restrict__ gs, const float* __restrict__ bs,
    __half* __restrict__ out)
{
    int row = blockIdx.x;
    const float* xr = x + (size_t)row * C;
    int t = threadIdx.x;
    float v0 = xr[t], v1 = xr[t + 256], v2 = xr[t + 512];
    float s = v0 + v1 + v2;
    float ss = v0 * v0 + v1 * v1 + v2 * v2;
    #pragma unroll
    for (int o = 16; o; o >>= 1) {
        s  += __shfl_xor_sync(0xffffffffu, s, o);
        ss += __shfl_xor_sync(0xffffffffu, ss, o);
    }
    __shared__ float sm[2][8];
    int warp = t >> 5, lane = t & 31;
    if (!lane) { sm[0][warp] = s; sm[1][warp] = ss; }
    __syncthreads();
    if (t < 32) {
        float a = (lane < 8) ? sm[0][lane] : 0.f;
        float b = (lane < 8) ? sm[1][lane] : 0.f;
        #pragma unroll
        for (int o = 4; o; o >>= 1) {
            a += __shfl_xor_sync(0xffffffffu, a, o);
            b += __shfl_xor_sync(0xffffffffu, b, o);
        }
        if (!lane) { sm[0][0] = a; sm[1][0] = b; }
    }
    __syncthreads();
    float mean = sm[0][0] * (1.0f / C);
    float var  = sm[1][0] * (1.0f / C) - mean * mean;
    float rstd = rsqrtf(var + 1e-5f);
    const float* g  = (row < TH) ? gl : gs;
    const float* bb = (row < TH) ? bl : bs;
    __half* orow = out + (size_t)row * C;
    orow[t]       = __float2half_rn((v0 - mean) * rstd * g[t]       + bb[t]);
    orow[t + 256] = __float2half_rn((v1 - mean) * rstd * g[t + 256] + bb[t + 256]);
    orow[t + 512] = __float2half_rn((v2 - mean) * rstd * g[t + 512] + bb[t + 512]);
}

// ---------------------------------------------------------------------------
// Transpose fp32 [K][N] -> half [N][K]; mode 1 applies gumbel channel masks
// (k = input dim index, n = output dim index of the projection).
// ---------------------------------------------------------------------------
__global__ void transpose_h(const float* __restrict__ in, __half* __restrict__ out,
                            int K, int N, const float* __restrict__ g, int mode)
{
    __shared__ float tile[32][33];
    int kb = blockIdx.y * 32, nb = blockIdx.x * 32;
    int tx = threadIdx.x, ty = threadIdx.y;   // 32 x 8
    #pragma unroll
    for (int j = 0; j < 32; j += 8)
        tile[ty + j][tx] = in[(size_t)(kb + ty + j) * N + nb + tx];
    __syncthreads();
    #pragma unroll
    for (int j = 0; j < 32; j += 8) {
        int n = nb + ty + j, k = kb + tx;
        float v = tile[tx][ty + j];
        if (mode) {
            float m = g[0];
            if (k < 384 && n < 384) m += g[1];
            if (k < 256 && n < 256) m += g[2];
            v *= m;
        }
        out[(size_t)n * K + k] = __float2half_rn(v);
    }
}

__global__ void beff_kernel(const float* __restrict__ b, const float* __restrict__ g,
                            float* __restrict__ beff)
{
    int i = blockIdx.x * blockDim.x + threadIdx.x;
    if (i < C) {
        float m = g[0];
        if (i < 384) m += g[1];
        if (i < 256) m += g[2];
        beff[i] = b[i] * m;
    }
}

// ---------------------------------------------------------------------------
// Attention: one block per (b, h). Half inputs; K stored as half2 words,
// V packed half2 (d, d+32). fp32 softmax/accumulation. Half output.
// ---------------------------------------------------------------------------
#define KPITCH 33
#define PSTRIDE 258

__global__ __launch_bounds__(256) void attn_kernel(
    const __half* __restrict__ qkv, __half* __restrict__ out)
{
    int bh = blockIdx.x;
    int b = bh / NH, h = bh % NH;
    uint32_t* Kw = (uint32_t*)dsmem;                    // 257*33 words
    uint32_t* Vp = Kw + NTOK * KPITCH;                  // 257*33 words
    float*    Psh = (float*)(Vp + NTOK * KPITCH);       // 8*258 f
    uint32_t* Qw  = (uint32_t*)(Psh + 8 * PSTRIDE);     // 8*32 words

    int tid = threadIdx.x, warp = tid >> 5, lane = tid & 31;
    const __half* base = qkv + (size_t)b * NTOK * (3 * C) + h * HD;

    for (int idx = tid; idx < NTOK * 32; idx += 256) {
        int m = idx >> 5, w = idx & 31;
        const __half* row = base + (size_t)m * (3 * C);
        __half2 kh = *(const __half2*)(row + C + 2 * w);
        Kw[m * KPITCH + w] = *(uint32_t*)&kh;
        const __half* vr = row + 2 * C;
        __half2 vh = __halves2half2(vr[w], vr[w + 32]);
        Vp[m * KPITCH + w] = *(uint32_t*)&vh;
    }
    __syncthreads();

    float* myP = Psh + warp * PSTRIDE;
    uint32_t* myQ = Qw + warp * 32;

    for (int n = warp; n < NTOK; n += 8) {
        const __half* qrow = base + (size_t)n * (3 * C);
        __half2 qh = *(const __half2*)(qrow + 2 * lane);
        myQ[lane] = *(uint32_t*)&qh;
        __syncwarp();

        float lmax = -1e30f;
        for (int m = lane; m < NTOK; m += 32) {
            const uint32_t* kr = &Kw[m * KPITCH];
            float s0 = 0.f, s1 = 0.f;
            #pragma unroll
            for (int w = 0; w < 32; w += 2) {
                float2 q0 = __half22float2(u32_as_h2(myQ[w]));
                float2 k0 = __half22float2(u32_as_h2(kr[w]));
                float2 q1 = __half22float2(u32_as_h2(myQ[w + 1]));
                float2 k1 = __half22float2(u32_as_h2(kr[w + 1]));
                s0 += q0.x * k0.x + q0.y * k0.y;
                s1 += q1.x * k1.x + q1.y * k1.y;
            }
            float s = (s0 + s1) * 0.125f;
            myP[m] = s;
            lmax = fmaxf(lmax, s);
        }
        #pragma unroll
        for (int o = 16; o; o >>= 1)
            lmax = fmaxf(lmax, __shfl_xor_sync(0xffffffffu, lmax, o));

        float lsum = 0.f;
        for (int m = lane; m < NTOK; m += 32) {
            float p = expf(myP[m] - lmax);
            myP[m] = p;
            lsum += p;
        }
        #pragma unroll
        for (int o = 16; o; o >>= 1)
            lsum += __shfl_xor_sync(0xffffffffu, lsum, o);
        __syncwarp();

        float a0[4] = {0.f, 0.f, 0.f, 0.f};
        float a1[4] = {0.f, 0.f, 0.f, 0.f};
        int m = 0;
        for (; m + 4 <= NTOK; m += 4) {
            #pragma unroll
            for (int u = 0; u < 4; u++) {
                float p = myP[m + u];
                float2 vf = __half22float2(u32_as_h2(Vp[(m + u) * KPITCH + lane]));
                a0[u] += p * vf.x;
                a1[u] += p * vf.y;
            }
        }
        for (; m < NTOK; m++) {
            float p = myP[m];
            float2 vf = __half22float2(u32_as_h2(Vp[m * KPITCH + lane]));
            a0[0] += p * vf.x;
            a1[0] += p * vf.y;
        }
        float inv = 1.0f / lsum;
        float o0 = (a0[0] + a0[1] + a0[2] + a0[3]) * inv;
        float o1 = (a1[0] + a1[1] + a1[2] + a1[3]) * inv;

        __half* orow = out + ((size_t)b * NTOK + n) * C + h * HD;
        orow[lane]      = __float2half_rn(o0);
        orow[lane + 32] = __float2half_rn(o1);
        __syncwarp();
    }
}

// ---------------------------------------------------------------------------
// Launch
// ---------------------------------------------------------------------------
static inline void* symv(const void* symbol) {
    void* p = nullptr;
    cudaGetSymbolAddress(&p, symbol);
    return p;
}

extern "C" void kernel_launch(void* const* d_in, const int* in_sizes, int n_in,
                              void* d_out, int out_size)
{
    const float* x      = (const float*)d_in[0];
    const float* gw     = (const float*)d_in[1];
    const float* n1l_g  = (const float*)d_in[2];
    const float* n1l_b  = (const float*)d_in[3];
    const float* n1s_g  = (const float*)d_in[4];
    const float* n1s_b  = (const float*)d_in[5];
    const float* w_qkv  = (const float*)d_in[6];
    const float* w_proj = (const float*)d_in[7];
    const float* b_proj = (const float*)d_in[8];
    const float* n2l_g  = (const float*)d_in[9];
    const float* n2l_b  = (const float*)d_in[10];
    const float* n2s_g  = (const float*)d_in[11];
    const float* n2s_b  = (const float*)d_in[12];
    const float* w_fc1  = (const float*)d_in[13];
    const float* b_fc1  = (const float*)d_in[14];
    const float* w_fc2  = (const float*)d_in[15];
    const float* b_fc2  = (const float*)d_in[16];
    float* out = (float*)d_out;

    __half* normed = (__half*)symv(g_normed_h);
    __half* qkv    = (__half*)symv(g_qkv_h);
    __half* attn   = (__half*)symv(g_attn_h);
    float*  x1     = (float*)symv(g_x1);
    float*  beff   = (float*)symv(g_beff);
    __half* hL     = (__half*)symv(g_hL_h);
    float*  pre2   = (float*)symv(g_pre2);
    float*  pre3   = (float*)symv(g_pre3);
    __half* h1h    = (__half*)symv(g_h1h);
    __half* h2h    = (__half*)symv(g_h2h);
    __half* h3h    = (__half*)symv(g_h3h);
    __half* wqkvT  = (__half*)symv(g_wqkvT);
    __half* wprojT = (__half*)symv(g_wprojT);
    __half* weffT  = (__half*)symv(g_weffT);
    __half* wfc1T  = (__half*)symv(g_wfc1T);
    __half* wfc2T  = (__half*)symv(g_wfc2T);

    const int attn_smem = (2 * NTOK * KPITCH + 8 * PSTRIDE + 8 * 32) * 4;
    cudaFuncSetAttribute(attn_kernel, cudaFuncAttributeMaxDynamicSharedMemorySize,
                         attn_smem);
    cudaFuncSetAttribute(hgemm_k, cudaFuncAttributeMaxDynamicSharedMemorySize,
                         GEMM_SMEM);

    const int MB_T  = (T  + 127) / 128;   // 129
    const int MB_TH = (TH + 127) / 128;   // 65
    dim3 tb(32, 8);

    // 0. weight prep: transpose + fp16 (+ gumbel fold for weffT)
    transpose_h<<<dim3(3 * C / 32, C / 32), tb>>>(w_qkv, wqkvT, C, 3 * C, nullptr, 0);
    transpose_h<<<dim3(C / 32, C / 32), tb>>>(w_proj, wprojT, C, C, nullptr, 0);
    transpose_h<<<dim3(C / 32, C / 32), tb>>>(w_proj, weffT, C, C, gw, 1);
    transpose_h<<<dim3(HID / 32, C / 32), tb>>>(w_fc1, wfc1T, C, HID, nullptr, 0);
    transpose_h<<<dim3(C / 32, HID / 32), tb>>>(w_fc2, wfc2T, HID, C, nullptr, 0);
    beff_kernel<<<3, 256>>>(b_proj, gw, beff);

    // 1. LN1
    ln_kernel<<<T, 256>>>(x, n1l_g, n1l_b, n1s_g, n1s_b, normed);

    // 2. QKV: (T x 768) @ WT(2304 x 768)
    hgemm_k<<<dim3(2304 / 128, MB_T), 256, GEMM_SMEM>>>(
        normed, C, wqkvT, C, qkv, 3 * C, 1,
        nullptr, 0, nullptr, nullptr, 0, T, C, nullptr, 0, 0, nullptr);

    // 3. Attention
    attn_kernel<<<BATCH * NH, 256, attn_smem>>>(qkv, attn);

    // 4. Projection + residual
    hgemm_k<<<dim3(C / 128, MB_TH), 256, GEMM_SMEM>>>(
        attn, C, wprojT, C, x1, C, 0,
        nullptr, 0, b_proj, x, C, TH, C, nullptr, 0, 0, nullptr);
    hgemm_k<<<dim3(C / 128, MB_TH), 256, GEMM_SMEM>>>(
        attn + (size_t)TH * C, C, weffT, C, x1 + (size_t)TH * C, C, 0,
        nullptr, 0, beff, x + (size_t)TH * C, C, TH, C, nullptr, 0, 0, nullptr);

    // 5. LN2
    ln_kernel<<<T, 256>>>(x1, n2l_g, n2l_b, n2s_g, n2s_b, normed);

    // 6. FC1
    hgemm_k<<<dim3(HID / 128, MB_TH), 256, GEMM_SMEM>>>(
        normed, C, wfc1T, C, hL, HID, 1,
        nullptr, 0, b_fc1, nullptr, 0, TH, C, nullptr, 0, 1, nullptr);
    const __half* ns2 = normed + (size_t)TH * C;
    // small partial-K chain: pre3 (K=256, fp32) -> pre2 (+K 256:384, gelu-backs
    // pre3 -> h3h) -> h1h (+K 384:768, fused gelu, gelu-backs pre2 -> h2h)
    hgemm_k<<<dim3(HID / 128, MB_TH), 256, GEMM_SMEM>>>(
        ns2, C, wfc1T, C, pre3, HID, 0,
        nullptr, 0, b_fc1, nullptr, 0, TH, 256, nullptr, 0, 0, nullptr);
    hgemm_k<<<dim3(HID / 128, MB_TH), 256, GEMM_SMEM>>>(
        ns2 + 256, C, wfc1T + 256, C, pre2, HID, 0,
        pre3, HID, nullptr, nullptr, 0, TH, 128, nullptr, 0, 0, h3h);
    hgemm_k<<<dim3(HID / 128, MB_TH), 256, GEMM_SMEM>>>(
        ns2 + 384, C, wfc1T + 384, C, h1h, HID, 1,
        pre2, HID, nullptr, nullptr, 0, TH, 384, nullptr, 0, 1, h2h);

    // 7. FC2
    hgemm_k<<<dim3(C / 128, MB_TH), 256, GEMM_SMEM>>>(
        hL, HID, wfc2T, HID, out, C, 0,
        nullptr, 0, b_fc2, x1, C, TH, HID, nullptr, 0, 0, nullptr);
    float* outS = out + (size_t)TH * C;
    const float* x1S = x1 + (size_t)TH * C;
    hgemm_k<<<dim3(C / 128, MB_TH), 256, GEMM_SMEM>>>(
        h1h, HID, wfc2T, HID, outS, C, 0,
        nullptr, 0, b_fc2, x1S, C, TH, HID, gw, 0, 0, nullptr);
    hgemm_k<<<dim3(384 / 128, MB_TH), 256, GEMM_SMEM>>>(
        h2h, HID, wfc2T, HID, outS, C, 0,
        outS, C, b_fc2, nullptr, 0, TH, HID, gw, 1, 0, nullptr);
    hgemm_k<<<dim3(256 / 128, MB_TH), 256, GEMM_SMEM>>>(
        h3h, HID, wfc2T, HID, outS, C, 0,
        outS, C, b_fc2, nullptr, 0, TH, HID, gw, 2, 0, nullptr);
}

// round 14
// speedup vs baseline: 6.1447x; 1.0575x over previous
#include <cuda_runtime.h>
#include <cuda_fp16.h>
#include <math.h>
#include <stdint.h>

// ---------------------------------------------------------------------------
// Problem constants
// ---------------------------------------------------------------------------
#define BATCH   64
#define B2      32
#define NTOK    257
#define C       768
#define HID     3072
#define NH      12
#define HD      64
#define T       (BATCH * NTOK)      // 16448 tokens total
#define TH      (B2 * NTOK)         // 8224 tokens per half

// ---------------------------------------------------------------------------
// Scratch (static device allocations; no cudaMalloc allowed)
// ---------------------------------------------------------------------------
__device__ __half g_normed_h[T * C];
__device__ __half g_qkv_h[T * 3 * C];
__device__ __half g_attn_h[T * C];
__device__ float  g_x1[T * C];
__device__ float  g_beff[C];
__device__ __half g_hL_h[TH * HID];
__device__ float  g_pre2[TH * HID];
__device__ float  g_pre3[TH * HID];
__device__ __half g_h1h[TH * HID];
__device__ __half g_h2h[TH * HID];
__device__ __half g_h3h[TH * HID];
__device__ float  g_P2[TH * 384];      // FC2 small partials (alpha folded)
__device__ float  g_P3[TH * 256];
// transposed fp16 weights: WT[n][k], k contiguous
__device__ __half g_wqkvT[3 * C * C];
__device__ __half g_wprojT[C * C];
__device__ __half g_weffT[C * C];
__device__ __half g_wfc1T[HID * C];
__device__ __half g_wfc2T[C * HID];

// ---------------------------------------------------------------------------
// Helpers
// ---------------------------------------------------------------------------
__device__ __forceinline__ float gelu_exact(float v) {
    return 0.5f * v * (1.0f + erff(v * 0.70710678118654752f));
}
__device__ __forceinline__ uint32_t smem_u32(const void* p) {
    uint32_t a;
    asm("{ .reg .u64 t; cvta.to.shared.u64 t, %1; cvt.u32.u64 %0, t; }"
        : "=r"(a) : "l"(p));
    return a;
}
__device__ __forceinline__ void cp_async16(uint32_t dst, const void* src, int srcbytes) {
    asm volatile("cp.async.cg.shared.global [%0], [%1], 16, %2;"
                 :: "r"(dst), "l"(src), "r"(srcbytes));
}
#define CP_COMMIT() asm volatile("cp.async.commit_group;" ::: "memory")
#define CP_WAIT3()  asm volatile("cp.async.wait_group 3;" ::: "memory")

__device__ __forceinline__ void mma_f16(float* c, const uint32_t* a, const uint32_t* b) {
    asm volatile(
        "mma.sync.aligned.m16n8k16.row.col.f32.f16.f16.f32 "
        "{%0,%1,%2,%3}, {%4,%5,%6,%7}, {%8,%9}, {%0,%1,%2,%3};"
        : "+f"(c[0]), "+f"(c[1]), "+f"(c[2]), "+f"(c[3])
        : "r"(a[0]), "r"(a[1]), "r"(a[2]), "r"(a[3]), "r"(b[0]), "r"(b[1]));
}
__device__ __forceinline__ void ldsm_x4(uint32_t* r, uint32_t addr) {
    asm volatile("ldmatrix.sync.aligned.m8n8.x4.shared.b16 {%0,%1,%2,%3}, [%4];"
        : "=r"(r[0]), "=r"(r[1]), "=r"(r[2]), "=r"(r[3]) : "r"(addr));
}
__device__ __forceinline__ void ldsm_x2(uint32_t* r, uint32_t addr) {
    asm volatile("ldmatrix.sync.aligned.m8n8.x2.shared.b16 {%0,%1}, [%2];"
        : "=r"(r[0]), "=r"(r[1]) : "r"(addr));
}
__device__ __forceinline__ __half2 u32_as_h2(uint32_t w) {
    return *reinterpret_cast<__half2*>(&w);
}

extern __shared__ char dsmem[];

// GEMM smem: A/B tiles 128 rows x 32 halves, pitch 40 halves (80B), 5 stages
#define APITCH_H 40
#define A_BYTES  (128 * APITCH_H * 2)   // 10240
#define STG_B    (2 * A_BYTES)          // 20480
#define STAGES   5
#define GEMM_SMEM (STAGES * STG_B)      // 102400

// ---------------------------------------------------------------------------
// Multi-task fp16 GEMM: flattened grid; each CTA resolves its task from the
// batch table (by-value kernel arg), then computes a 128x128 tile.
// ---------------------------------------------------------------------------
struct GemmTask {
    const __half* A; const __half* B;
    void* Cc; const float* Cin;
    const float* bias; const float* resid;
    const float* alpha_ptr; __half* gback;
    int lda, ldb, ldc, out_half, ldcin, ldr;
    int M, K, aidx, do_gelu, bnCnt, ctaStart;
};
struct GemmBatch { GemmTask t[4]; int n; };

__global__ void __launch_bounds__(256, 2) hgemm_multi(GemmBatch nb)
{
    const int bid = blockIdx.x;
    int ti = 0;
    #pragma unroll
    for (int j = 1; j < 4; j++)
        if (j < nb.n && bid >= nb.t[j].ctaStart) ti = j;
    const GemmTask& tk = nb.t[ti];
    const int local = bid - tk.ctaStart;
    const int bn = local % tk.bnCnt;
    const int bm = local / tk.bnCnt;

    const int tid = threadIdx.x;
    const int wid = tid >> 5, lid = tid & 31;
    const int warpM = wid >> 2;          // 0..1  (64 rows)
    const int warpN = wid & 3;           // 0..3  (32 cols)
    const int lq = lid >> 2;             // 0..7
    const int lr = lid & 3;              // 0..3

    const uint32_t sbase = smem_u32(dsmem);
    const int ldRow = tid >> 2;          // 0..63 (+64)
    const int ldQ   = tid & 3;

    // ldmatrix lane address components
    const int aRowSel = (lid & 7) + ((lid >> 3) & 1) * 8;
    const int aKb16   = ((lid >> 4) & 1) * 16;
    const int bRowSel = lid & 7;
    const int bKb16   = ((lid >> 3) & 1) * 16;

    float acc[4][4][4];
    #pragma unroll
    for (int mi = 0; mi < 4; mi++)
        #pragma unroll
        for (int ni = 0; ni < 4; ni++)
            #pragma unroll
            for (int j = 0; j < 4; j++) acc[mi][ni][j] = 0.f;

    const __half* A = tk.A; const __half* B = tk.B;
    const int lda = tk.lda, ldb = tk.ldb, M = tk.M;
    const int nch = tk.K >> 5;

    auto issue = [&](int ci, int st) {
        int k0 = ci << 5;
        uint32_t aB = sbase + (uint32_t)st * STG_B;
        uint32_t bB = aB + A_BYTES;
        #pragma unroll
        for (int u = 0; u < 2; u++) {
            int row = ldRow + u * 64;
            int r = bm * 128 + row;
            bool ok = (r < M);
            const __half* src = A + (size_t)(ok ? r : 0) * lda + k0 + ldQ * 8;
            cp_async16(aB + (uint32_t)(row * 80 + ldQ * 16), src, ok ? 16 : 0);
        }
        #pragma unroll
        for (int u = 0; u < 2; u++) {
            int row = ldRow + u * 64;
            const __half* src = B + (size_t)(bn * 128 + row) * ldb + k0 + ldQ * 8;
            cp_async16(bB + (uint32_t)(row * 80 + ldQ * 16), src, 16);
        }
    };

    #pragma unroll
    for (int s = 0; s < STAGES - 1; s++) {
        if (s < nch) issue(s, s);
        CP_COMMIT();
    }

    for (int i = 0; i < nch; i++) {
        CP_WAIT3();
        __syncthreads();
        int nx = i + STAGES - 1;
        if (nx < nch) issue(nx, nx % STAGES);
        CP_COMMIT();

        int st = i % STAGES;
        uint32_t aStage = sbase + (uint32_t)st * STG_B;
        uint32_t bStage = aStage + A_BYTES;

        #pragma unroll
        for (int ks = 0; ks < 2; ks++) {
            uint32_t afr[4][4], bfr[4][2];
            #pragma unroll
            for (int mi = 0; mi < 4; mi++) {
                int row = warpM * 64 + mi * 16 + aRowSel;
                ldsm_x4(afr[mi], aStage + (uint32_t)(row * 80 + ks * 32 + aKb16));
            }
            #pragma unroll
            for (int ni = 0; ni < 4; ni++) {
                int row = warpN * 32 + ni * 8 + bRowSel;
                ldsm_x2(bfr[ni], bStage + (uint32_t)(row * 80 + ks * 32 + bKb16));
            }
            #pragma unroll
            for (int mi = 0; mi < 4; mi++)
                #pragma unroll
                for (int ni = 0; ni < 4; ni++)
                    mma_f16(acc[mi][ni], afr[mi], bfr[ni]);
        }
    }

    // ---- epilogue ----
    float alpha = tk.alpha_ptr ? tk.alpha_ptr[tk.aidx] : 1.0f;
    #pragma unroll
    for (int mi = 0; mi < 4; mi++) {
        #pragma unroll
        for (int h = 0; h < 2; h++) {
            int r = bm * 128 + warpM * 64 + mi * 16 + lq + h * 8;
            if (r >= M) continue;
            #pragma unroll
            for (int ni = 0; ni < 4; ni++) {
                int cc = bn * 128 + warpN * 32 + ni * 8 + lr * 2;
                float v0 = acc[mi][ni][h * 2 + 0];
                float v1 = acc[mi][ni][h * 2 + 1];
                if (tk.bias) { v0 += tk.bias[cc]; v1 += tk.bias[cc + 1]; }
                v0 *= alpha; v1 *= alpha;
                if (tk.Cin) {
                    const float* cp = tk.Cin + (size_t)r * tk.ldcin + cc;
                    float c0 = cp[0], c1 = cp[1];
                    v0 += c0; v1 += c1;
                    if (tk.gback) {
                        __half2* gp = (__half2*)(tk.gback + (size_t)r * tk.ldcin + cc);
                        *gp = __floats2half2_rn(gelu_exact(c0), gelu_exact(c1));
                    }
                }
                if (tk.resid) {
                    const float* rp = tk.resid + (size_t)r * tk.ldr + cc;
                    v0 += rp[0]; v1 += rp[1];
                }
                if (tk.do_gelu) { v0 = gelu_exact(v0); v1 = gelu_exact(v1); }
                if (tk.out_half) {
                    __half2* op = (__half2*)((__half*)tk.Cc + (size_t)r * tk.ldc + cc);
                    *op = __floats2half2_rn(v0, v1);
                } else {
                    float2* op = (float2*)((float*)tk.Cc + (size_t)r * tk.ldc + cc);
                    *op = make_float2(v0, v1);
                }
            }
        }
    }
}

// ---------------------------------------------------------------------------
// FC2-small merge: outS[:, :384] += P2; outS[:, :256] += P3 (alphas folded)
// ---------------------------------------------------------------------------
__global__ void merge_kernel(float* __restrict__ outS,
                             const float* __restrict__ P2,
                             const float* __restrict__ P3)
{
    int i = blockIdx.x * blockDim.x + threadIdx.x;   // over TH*96 float4s
    if (i >= TH * 96) return;
    int r = i / 96, c4 = i % 96;
    float4 v = *(float4*)(outS + (size_t)r * C + c4 * 4);
    float4 p2 = *(const float4*)(P2 + (size_t)r * 384 + c4 * 4);
    v.x += p2.x; v.y += p2.y; v.z += p2.z; v.w += p2.w;
    if (c4 < 64) {
        float4 p3 = *(const float4*)(P3 + (size_t)r * 256 + c4 * 4);
        v.x += p3.x; v.y += p3.y; v.z += p3.z; v.w += p3.w;
    }
    *(float4*)(outS + (size_t)r * C + c4 * 4) = v;
}

// ---------------------------------------------------------------------------
// LayerNorm: fp32 in, half out
// ---------------------------------------------------------------------------
__global__ __launch_bounds__(256) void ln_kernel(
    const float* __restrict__ x,
    const float* __restrict__ gl, const float* __restrict__ bl,
    const float* __restrict__ gs, const float* __restrict__ bs,
    __half* __restrict__ out)
{
    int row = blockIdx.x;
    const float* xr = x + (size_t)row * C;
    int t = threadIdx.x;
    float v0 = xr[t], v1 = xr[t + 256], v2 = xr[t + 512];
    float s = v0 + v1 + v2;
    float ss = v0 * v0 + v1 * v1 + v2 * v2;
    #pragma unroll
    for (int o = 16; o; o >>= 1) {
        s  += __shfl_xor_sync(0xffffffffu, s, o);
        ss += __shfl_xor_sync(0xffffffffu, ss, o);
    }
    __shared__ float sm[2][8];
    int warp = t >> 5, lane = t & 31;
    if (!lane) { sm[0][warp] = s; sm[1][warp] = ss; }
    __syncthreads();
    if (t < 32) {
        float a = (lane < 8) ? sm[0][lane] : 0.f;
        float b = (lane < 8) ? sm[1][lane] : 0.f;
        #pragma unroll
        for (int o = 4; o; o >>= 1) {
            a += __shfl_xor_sync(0xffffffffu, a, o);
            b += __shfl_xor_sync(0xffffffffu, b, o);
        }
        if (!lane) { sm[0][0] = a; sm[1][0] = b; }
    }
    __syncthreads();
    float mean = sm[0][0] * (1.0f / C);
    float var  = sm[1][0] * (1.0f / C) - mean * mean;
    float rstd = rsqrtf(var + 1e-5f);
    const float* g  = (row < TH) ? gl : gs;
    const float* bb = (row < TH) ? bl : bs;
    __half* orow = out + (size_t)row * C;
    orow[t]       = __float2half_rn((v0 - mean) * rstd * g[t]       + bb[t]);
    orow[t + 256] = __float2half_rn((v1 - mean) * rstd * g[t + 256] + bb[t + 256]);
    orow[t + 512] = __float2half_rn((v2 - mean) * rstd * g[t + 512] + bb[t + 512]);
}

// ---------------------------------------------------------------------------
// Transpose fp32 [K][N] -> half [N][K]; mode 1 applies gumbel channel masks
// ---------------------------------------------------------------------------
__global__ void transpose_h(const float* __restrict__ in, __half* __restrict__ out,
                            int K, int N, const float* __restrict__ g, int mode)
{
    __shared__ float tile[32][33];
    int kb = blockIdx.y * 32, nb = blockIdx.x * 32;
    int tx = threadIdx.x, ty = threadIdx.y;   // 32 x 8
    #pragma unroll
    for (int j = 0; j < 32; j += 8)
        tile[ty + j][tx] = in[(size_t)(kb + ty + j) * N + nb + tx];
    __syncthreads();
    #pragma unroll
    for (int j = 0; j < 32; j += 8) {
        int n = nb + ty + j, k = kb + tx;
        float v = tile[tx][ty + j];
        if (mode) {
            float m = g[0];
            if (k < 384 && n < 384) m += g[1];
            if (k < 256 && n < 256) m += g[2];
            v *= m;
        }
        out[(size_t)n * K + k] = __float2half_rn(v);
    }
}

__global__ void beff_kernel(const float* __restrict__ b, const float* __restrict__ g,
                            float* __restrict__ beff)
{
    int i = blockIdx.x * blockDim.x + threadIdx.x;
    if (i < C) {
        float m = g[0];
        if (i < 384) m += g[1];
        if (i < 256) m += g[2];
        beff[i] = b[i] * m;
    }
}

// ---------------------------------------------------------------------------
// Attention: one block per (b, h). Half in/out, fp32 softmax.
// ---------------------------------------------------------------------------
#define KPITCH 33
#define PSTRIDE 258

__global__ __launch_bounds__(256) void attn_kernel(
    const __half* __restrict__ qkv, __half* __restrict__ out)
{
    int bh = blockIdx.x;
    int b = bh / NH, h = bh % NH;
    uint32_t* Kw = (uint32_t*)dsmem;
    uint32_t* Vp = Kw + NTOK * KPITCH;
    float*    Psh = (float*)(Vp + NTOK * KPITCH);
    uint32_t* Qw  = (uint32_t*)(Psh + 8 * PSTRIDE);

    int tid = threadIdx.x, warp = tid >> 5, lane = tid & 31;
    const __half* base = qkv + (size_t)b * NTOK * (3 * C) + h * HD;

    for (int idx = tid; idx < NTOK * 32; idx += 256) {
        int m = idx >> 5, w = idx & 31;
        const __half* row = base + (size_t)m * (3 * C);
        __half2 kh = *(const __half2*)(row + C + 2 * w);
        Kw[m * KPITCH + w] = *(uint32_t*)&kh;
        const __half* vr = row + 2 * C;
        __half2 vh = __halves2half2(vr[w], vr[w + 32]);
        Vp[m * KPITCH + w] = *(uint32_t*)&vh;
    }
    __syncthreads();

    float* myP = Psh + warp * PSTRIDE;
    uint32_t* myQ = Qw + warp * 32;

    for (int n = warp; n < NTOK; n += 8) {
        const __half* qrow = base + (size_t)n * (3 * C);
        __half2 qh = *(const __half2*)(qrow + 2 * lane);
        myQ[lane] = *(uint32_t*)&qh;
        __syncwarp();

        float lmax = -1e30f;
        for (int m = lane; m < NTOK; m += 32) {
            const uint32_t* kr = &Kw[m * KPITCH];
            float s0 = 0.f, s1 = 0.f;
            #pragma unroll
            for (int w = 0; w < 32; w += 2) {
                float2 q0 = __half22float2(u32_as_h2(myQ[w]));
                float2 k0 = __half22float2(u32_as_h2(kr[w]));
                float2 q1 = __half22float2(u32_as_h2(myQ[w + 1]));
                float2 k1 = __half22float2(u32_as_h2(kr[w + 1]));
                s0 += q0.x * k0.x + q0.y * k0.y;
                s1 += q1.x * k1.x + q1.y * k1.y;
            }
            float s = (s0 + s1) * 0.125f;
            myP[m] = s;
            lmax = fmaxf(lmax, s);
        }
        #pragma unroll
        for (int o = 16; o; o >>= 1)
            lmax = fmaxf(lmax, __shfl_xor_sync(0xffffffffu, lmax, o));

        float lsum = 0.f;
        for (int m = lane; m < NTOK; m += 32) {
            float p = expf(myP[m] - lmax);
            myP[m] = p;
            lsum += p;
        }
        #pragma unroll
        for (int o = 16; o; o >>= 1)
            lsum += __shfl_xor_sync(0xffffffffu, lsum, o);
        __syncwarp();

        float a0[4] = {0.f, 0.f, 0.f, 0.f};
        float a1[4] = {0.f, 0.f, 0.f, 0.f};
        int m = 0;
        for (; m + 4 <= NTOK; m += 4) {
            #pragma unroll
            for (int u = 0; u < 4; u++) {
                float p = myP[m + u];
                float2 vf = __half22float2(u32_as_h2(Vp[(m + u) * KPITCH + lane]));
                a0[u] += p * vf.x;
                a1[u] += p * vf.y;
            }
        }
        for (; m < NTOK; m++) {
            float p = myP[m];
            float2 vf = __half22float2(u32_as_h2(Vp[m * KPITCH + lane]));
            a0[0] += p * vf.x;
            a1[0] += p * vf.y;
        }
        float inv = 1.0f / lsum;
        float o0 = (a0[0] + a0[1] + a0[2] + a0[3]) * inv;
        float o1 = (a1[0] + a1[1] + a1[2] + a1[3]) * inv;

        __half* orow = out + ((size_t)b * NTOK + n) * C + h * HD;
        orow[lane]      = __float2half_rn(o0);
        orow[lane + 32] = __float2half_rn(o1);
        __syncwarp();
    }
}

// ---------------------------------------------------------------------------
// Launch
// ---------------------------------------------------------------------------
static inline void* symv(const void* symbol) {
    void* p = nullptr;
    cudaGetSymbolAddress(&p, symbol);
    return p;
}

static GemmTask mk_task(const __half* A, int lda, const __half* B, int ldb,
                        void* Cc, int ldc, int out_half,
                        const float* Cin, int ldcin,
                        const float* bias, const float* resid, int ldr,
                        int M, int K, int N,
                        const float* alpha_ptr, int aidx, int do_gelu,
                        __half* gback)
{
    GemmTask t;
    t.A = A; t.lda = lda; t.B = B; t.ldb = ldb;
    t.Cc = Cc; t.ldc = ldc; t.out_half = out_half;
    t.Cin = Cin; t.ldcin = ldcin; t.bias = bias;
    t.resid = resid; t.ldr = ldr;
    t.M = M; t.K = K;
    t.alpha_ptr = alpha_ptr; t.aidx = aidx; t.do_gelu = do_gelu;
    t.gback = gback;
    t.bnCnt = N / 128; t.ctaStart = 0;
    return t;
}

static void launch_batch(GemmTask* tasks, int n)
{
    GemmBatch nb;
    int total = 0;
    for (int i = 0; i < n; i++) {
        tasks[i].ctaStart = total;
        total += tasks[i].bnCnt * ((tasks[i].M + 127) / 128);
        nb.t[i] = tasks[i];
    }
    nb.n = n;
    for (int i = n; i < 4; i++) nb.t[i] = tasks[n - 1];
    hgemm_multi<<<total, 256, GEMM_SMEM>>>(nb);
}

extern "C" void kernel_launch(void* const* d_in, const int* in_sizes, int n_in,
                              void* d_out, int out_size)
{
    const float* x      = (const float*)d_in[0];
    const float* gw     = (const float*)d_in[1];
    const float* n1l_g  = (const float*)d_in[2];
    const float* n1l_b  = (const float*)d_in[3];
    const float* n1s_g  = (const float*)d_in[4];
    const float* n1s_b  = (const float*)d_in[5];
    const float* w_qkv  = (const float*)d_in[6];
    const float* w_proj = (const float*)d_in[7];
    const float* b_proj = (const float*)d_in[8];
    const float* n2l_g  = (const float*)d_in[9];
    const float* n2l_b  = (const float*)d_in[10];
    const float* n2s_g  = (const float*)d_in[11];
    const float* n2s_b  = (const float*)d_in[12];
    const float* w_fc1  = (const float*)d_in[13];
    const float* b_fc1  = (const float*)d_in[14];
    const float* w_fc2  = (const float*)d_in[15];
    const float* b_fc2  = (const float*)d_in[16];
    float* out = (float*)d_out;

    __half* normed = (__half*)symv(g_normed_h);
    __half* qkv    = (__half*)symv(g_qkv_h);
    __half* attn   = (__half*)symv(g_attn_h);
    float*  x1     = (float*)symv(g_x1);
    float*  beff   = (float*)symv(g_beff);
    __half* hL     = (__half*)symv(g_hL_h);
    float*  pre2   = (float*)symv(g_pre2);
    float*  pre3   = (float*)symv(g_pre3);
    __half* h1h    = (__half*)symv(g_h1h);
    __half* h2h    = (__half*)symv(g_h2h);
    __half* h3h    = (__half*)symv(g_h3h);
    float*  P2     = (float*)symv(g_P2);
    float*  P3     = (float*)symv(g_P3);
    __half* wqkvT  = (__half*)symv(g_wqkvT);
    __half* wprojT = (__half*)symv(g_wprojT);
    __half* weffT  = (__half*)symv(g_weffT);
    __half* wfc1T  = (__half*)symv(g_wfc1T);
    __half* wfc2T  = (__half*)symv(g_wfc2T);

    const int attn_smem = (2 * NTOK * KPITCH + 8 * PSTRIDE + 8 * 32) * 4;
    cudaFuncSetAttribute(attn_kernel, cudaFuncAttributeMaxDynamicSharedMemorySize,
                         attn_smem);
    cudaFuncSetAttribute(hgemm_multi, cudaFuncAttributeMaxDynamicSharedMemorySize,
                         GEMM_SMEM);

    dim3 tb(32, 8);

    // 0. weight prep
    transpose_h<<<dim3(3 * C / 32, C / 32), tb>>>(w_qkv, wqkvT, C, 3 * C, nullptr, 0);
    transpose_h<<<dim3(C / 32, C / 32), tb>>>(w_proj, wprojT, C, C, nullptr, 0);
    transpose_h<<<dim3(C / 32, C / 32), tb>>>(w_proj, weffT, C, C, gw, 1);
    transpose_h<<<dim3(HID / 32, C / 32), tb>>>(w_fc1, wfc1T, C, HID, nullptr, 0);
    transpose_h<<<dim3(C / 32, HID / 32), tb>>>(w_fc2, wfc2T, HID, C, nullptr, 0);
    beff_kernel<<<3, 256>>>(b_proj, gw, beff);

    // 1. LN1
    ln_kernel<<<T, 256>>>(x, n1l_g, n1l_b, n1s_g, n1s_b, normed);

    // 2. QKV
    {
        GemmTask t[1] = { mk_task(normed, C, wqkvT, C, qkv, 3 * C, 1,
                                  nullptr, 0, nullptr, nullptr, 0,
                                  T, C, 3 * C, nullptr, 0, 0, nullptr) };
        launch_batch(t, 1);
    }

    // 3. Attention
    attn_kernel<<<BATCH * NH, 256, attn_smem>>>(qkv, attn);

    // 4. Projection + residual (large + small concurrently)
    {
        GemmTask t[2] = {
            mk_task(attn, C, wprojT, C, x1, C, 0,
                    nullptr, 0, b_proj, x, C, TH, C, C, nullptr, 0, 0, nullptr),
            mk_task(attn + (size_t)TH * C, C, weffT, C,
                    x1 + (size_t)TH * C, C, 0,
                    nullptr, 0, beff, x + (size_t)TH * C, C, TH, C, C,
                    nullptr, 0, 0, nullptr) };
        launch_batch(t, 2);
    }

    // 5. LN2
    ln_kernel<<<T, 256>>>(x1, n2l_g, n2l_b, n2s_g, n2s_b, normed);

    // 6. FC1: large + pre3 concurrently, then dependent chain
    const __half* ns2 = normed + (size_t)TH * C;
    {
        GemmTask t[2] = {
            mk_task(normed, C, wfc1T, C, hL, HID, 1,
                    nullptr, 0, b_fc1, nullptr, 0, TH, C, HID,
                    nullptr, 0, 1, nullptr),
            mk_task(ns2, C, wfc1T, C, pre3, HID, 0,
                    nullptr, 0, b_fc1, nullptr, 0, TH, 256, HID,
                    nullptr, 0, 0, nullptr) };
        launch_batch(t, 2);
    }
    {
        GemmTask t[1] = { mk_task(ns2 + 256, C, wfc1T + 256, C, pre2, HID, 0,
                                  pre3, HID, nullptr, nullptr, 0, TH, 128, HID,
                                  nullptr, 0, 0, h3h) };
        launch_batch(t, 1);
    }
    {
        GemmTask t[1] = { mk_task(ns2 + 384, C, wfc1T + 384, C, h1h, HID, 1,
                                  pre2, HID, nullptr, nullptr, 0, TH, 384, HID,
                                  nullptr, 0, 1, h2h) };
        launch_batch(t, 1);
    }

    // 7. FC2: all four tasks concurrent; smalls 2/3 go to partial buffers
    float* outS = out + (size_t)TH * C;
    const float* x1S = x1 + (size_t)TH * C;
    {
        GemmTask t[4] = {
            mk_task(hL, HID, wfc2T, HID, out, C, 0,
                    nullptr, 0, b_fc2, x1, C, TH, HID, C, nullptr, 0, 0, nullptr),
            mk_task(h1h, HID, wfc2T, HID, outS, C, 0,
                    nullptr, 0, b_fc2, x1S, C, TH, HID, C, gw, 0, 0, nullptr),
            mk_task(h2h, HID, wfc2T, HID, P2, 384, 0,
                    nullptr, 0, b_fc2, nullptr, 0, TH, HID, 384, gw, 1, 0, nullptr),
            mk_task(h3h, HID, wfc2T, HID, P3, 256, 0,
                    nullptr, 0, b_fc2, nullptr, 0, TH, HID, 256, gw, 2, 0, nullptr) };
        launch_batch(t, 4);
    }
    merge_kernel<<<(TH * 96 + 255) / 256, 256>>>(outS, P2, P3);
}